// round 12
// baseline (speedup 1.0000x reference)
#include <cuda_runtime.h>
#include <cuda_fp16.h>
#include <cstdint>

// LCA layer via mma.sync (HMMA), factored + precision-budgeted:
//   b = x@W (2-term) ; u1 = 0.1 b ; 9x { t = a@W^T (fp16) ; u-upd via tW (fp16) }
//   out = a@W^T (2-term)
// R12: warp tile 64x64 (4-warp CTAs, 2x2), 2 CTAs/SM. 8 LDSM -> 32/64 HMMA
//      per k16. Same math as R11 (rel_err 2.6e-4 expected).

#define MDIM   8192
#define DMODEL 1024
#define DLCA   4096
#define LAMV   0.1f
#define RATEV  0.1f

// ---- 2-term geometry (KC=32, 64B rows, swizzle c^((r>>1)&3)) ----
#define KC2    32
#define ROWB2  64
#define T2_B   (128 * ROWB2)         // 8192
#define STAGE2 (3 * T2_B)            // Ah Bh Bl = 24576
#define NST2   4
#define SMEM2T (NST2 * STAGE2)       // 98304

// ---- 1-term geometry (KC=64, 128B rows, SW128 c^(r&7)) ----
#define KC1    64
#define ROWB1  128
#define T1_B   (128 * ROWB1)         // 16384
#define STAGE1 (2 * T1_B)            // 32768
#define SMEM1  (3 * STAGE1)          // 98304

// fp32 state
__device__ __align__(16) float g_b[(size_t)MDIM * DLCA];
__device__ __align__(16) float g_u[(size_t)MDIM * DLCA];
__device__ float g_diag[DLCA];
// fp16 operands
__device__ __align__(16) __half g_ahi[(size_t)MDIM * DLCA];
__device__ __align__(16) __half g_thi[(size_t)MDIM * DMODEL];
__device__ __align__(16) __half g_xhi[(size_t)MDIM * DMODEL];
__device__ __align__(16) __half g_Whi[(size_t)DMODEL * DLCA];
__device__ __align__(16) __half g_Wlo[(size_t)DMODEL * DLCA];
__device__ __align__(16) __half g_Wthi[(size_t)DLCA * DMODEL];
__device__ __align__(16) __half g_Wtlo[(size_t)DLCA * DMODEL];

__device__ __forceinline__ uint32_t smem_u32(const void* p) {
    uint32_t a;
    asm("{ .reg .u64 t; cvta.to.shared.u64 t, %1; cvt.u32.u64 %0, t; }" : "=r"(a) : "l"(p));
    return a;
}
__device__ __forceinline__ void ldsm4(uint32_t r[4], uint32_t addr) {
    asm volatile("ldmatrix.sync.aligned.m8n8.x4.shared.b16 {%0,%1,%2,%3}, [%4];"
                 : "=r"(r[0]), "=r"(r[1]), "=r"(r[2]), "=r"(r[3]) : "r"(addr));
}
__device__ __forceinline__ void mma16816(float c[4], const uint32_t a[4], const uint32_t b[2]) {
    asm volatile("mma.sync.aligned.m16n8k16.row.col.f32.f16.f16.f32 "
                 "{%0,%1,%2,%3}, {%4,%5,%6,%7}, {%8,%9}, {%0,%1,%2,%3};"
                 : "+f"(c[0]), "+f"(c[1]), "+f"(c[2]), "+f"(c[3])
                 : "r"(a[0]), "r"(a[1]), "r"(a[2]), "r"(a[3]), "r"(b[0]), "r"(b[1]));
}
#define CP_ASYNC(dst, src) \
    asm volatile("cp.async.cg.shared.global [%0], [%1], 16;" :: "r"(dst), "l"(src) : "memory")
#define CP_COMMIT() asm volatile("cp.async.commit_group;" ::: "memory")
#define CP_WAIT1()  asm volatile("cp.async.wait_group 1;" ::: "memory")
#define CP_WAIT2()  asm volatile("cp.async.wait_group 2;" ::: "memory")

// ---------------- prep kernels ----------------
__global__ void split_x_kernel(const float* __restrict__ x) {
    size_t i = (size_t)blockIdx.x * blockDim.x + threadIdx.x;
    g_xhi[i] = __float2half_rn(x[i]);
}
__global__ void splitW_kernel(const float* __restrict__ W) {
    __shared__ float tile[32][33];
    int n0 = blockIdx.x * 32, k0 = blockIdx.y * 32;
    int tx = threadIdx.x, ty = threadIdx.y;
    #pragma unroll
    for (int r = 0; r < 4; r++) {
        int k = k0 + ty + r * 8;
        float v = W[(size_t)k * DLCA + n0 + tx];
        __half h = __float2half_rn(v);
        g_Whi[(size_t)k * DLCA + n0 + tx] = h;
        g_Wlo[(size_t)k * DLCA + n0 + tx] = __float2half_rn(v - __half2float(h));
        tile[ty + r * 8][tx] = v;
    }
    __syncthreads();
    #pragma unroll
    for (int r = 0; r < 4; r++) {
        int n = n0 + ty + r * 8;
        float v = tile[tx][ty + r * 8];
        __half h = __float2half_rn(v);
        g_Wthi[(size_t)n * DMODEL + k0 + tx] = h;
        g_Wtlo[(size_t)n * DMODEL + k0 + tx] = __float2half_rn(v - __half2float(h));
    }
}
__global__ void diag_kernel(const float* __restrict__ W) {
    int j = blockIdx.x * blockDim.x + threadIdx.x;
    float s = 0.0f;
    #pragma unroll 8
    for (int k = 0; k < DMODEL; k++) {
        float w = W[(size_t)k * DLCA + j];
        s = fmaf(w, w, s);
    }
    g_diag[j] = s;
}

// ===================== 2-term GEMM (KC=32, 4-stage) =====================
// D = Ah*(Bh + Bl).  EPI 0: b-init (A=xhi, B=Wt, K=1024, Nout=4096)
//                    EPI 2: out    (A=ahi, B=W,  K=4096, Nout=1024)
template <int EPI>
__global__ __launch_bounds__(128, 2)
void lca_gemm2t(float* __restrict__ outp)
{
    constexpr int Kdim = (EPI == 2) ? DLCA : DMODEL;
    constexpr int Nout = (EPI == 2) ? DMODEL : DLCA;
    constexpr int NC   = Kdim / KC2;

    const __half* Ahp = (EPI == 0) ? g_xhi : g_ahi;
    const __half* Bhp = (EPI == 2) ? g_Whi : g_Wthi;
    const __half* Blp = (EPI == 2) ? g_Wlo : g_Wtlo;

    extern __shared__ __align__(16) char smem[];
    const uint32_t sbase = smem_u32(smem);

    const int tid = threadIdx.x;
    const int wid = tid >> 5, l = tid & 31;
    const int wm = wid >> 1, wn = wid & 1;     // warp grid 2(m) x 2(n), tile 64x64
    const int mBase = blockIdx.y * 128;
    const int nBase = blockIdx.x * 128;

    const __half* Ah = Ahp + (size_t)mBase * Kdim;
    const __half* Bh = Bhp + (size_t)nBase * Kdim;
    const __half* Bl = Blp + (size_t)nBase * Kdim;

    auto load_stage = [&](int s, int k0) {
        uint32_t sb = sbase + s * STAGE2;
        #pragma unroll
        for (int i = 0; i < 4; i++) {
            int u = tid + i * 128;            // 0..511
            int r = u >> 2, cc = u & 3;
            uint32_t so = r * ROWB2 + (cc ^ ((r >> 1) & 3)) * 16;
            size_t   go = (size_t)r * Kdim + k0 + cc * 8;
            CP_ASYNC(sb + so, Ah + go);
            CP_ASYNC(sb + T2_B + so, Bh + go);
            CP_ASYNC(sb + 2 * T2_B + so, Bl + go);
        }
    };

    float acc[4][8][4];
    #pragma unroll
    for (int a = 0; a < 4; a++)
        #pragma unroll
        for (int b = 0; b < 8; b++)
            #pragma unroll
            for (int c = 0; c < 4; c++) acc[a][b][c] = 0.0f;

    const int rowA = wm * 64 + (l & 15);
    const uint32_t sA = (uint32_t)((rowA >> 1) & 3);
    const uint32_t aRow = (uint32_t)rowA * ROWB2;
    const int colA0 = l >> 4;
    const int gB = l >> 3;
    const int rowB = wn * 64 + (l & 7) + (gB >> 1) * 8;
    const uint32_t sB = (uint32_t)((rowB >> 1) & 3);
    const uint32_t bRow = (uint32_t)rowB * ROWB2;
    const int colB0 = gB & 1;

    load_stage(0, 0);       CP_COMMIT();
    load_stage(1, KC2);     CP_COMMIT();
    load_stage(2, 2 * KC2); CP_COMMIT();

    for (int c = 0; c < NC; c++) {
        CP_WAIT2();
        __syncthreads();
        if (c + 3 < NC) load_stage((c + 3) % NST2, (c + 3) * KC2);
        CP_COMMIT();

        uint32_t st = sbase + (c % NST2) * STAGE2;
        #pragma unroll
        for (int k16 = 0; k16 < 2; k16++) {
            const uint32_t cA = (uint32_t)((colA0 + k16 * 2)) ^ sA;
            const uint32_t cB = (uint32_t)((colB0 + k16 * 2)) ^ sB;
            uint32_t aH = st + aRow + cA * 16;
            uint32_t bH = st + T2_B + bRow + cB * 16;
            uint32_t bL = st + 2 * T2_B + bRow + cB * 16;
            uint32_t ah[4][4], bh[4][4], bl[4][4];
            #pragma unroll
            for (int mt = 0; mt < 4; mt++) ldsm4(ah[mt], aH + mt * (16 * ROWB2));
            #pragma unroll
            for (int p = 0; p < 4; p++)    ldsm4(bh[p], bH + p * (16 * ROWB2));
            #pragma unroll
            for (int mt = 0; mt < 4; mt++)
                #pragma unroll
                for (int nt = 0; nt < 8; nt++)
                    mma16816(acc[mt][nt], ah[mt], &bh[nt >> 1][(nt & 1) * 2]);
            #pragma unroll
            for (int p = 0; p < 4; p++)    ldsm4(bl[p], bL + p * (16 * ROWB2));
            #pragma unroll
            for (int mt = 0; mt < 4; mt++)
                #pragma unroll
                for (int nt = 0; nt < 8; nt++)
                    mma16816(acc[mt][nt], ah[mt], &bl[nt >> 1][(nt & 1) * 2]);
        }
    }

    const int rb = wm * 64 + (l >> 2);
    const int cb = wn * 64 + 2 * (l & 3);
    #pragma unroll
    for (int mt = 0; mt < 4; mt++)
        #pragma unroll
        for (int i2 = 0; i2 < 2; i2++) {
            int row = mBase + rb + mt * 16 + i2 * 8;
            #pragma unroll
            for (int nt = 0; nt < 8; nt++) {
                int col = nBase + cb + nt * 8;
                size_t idx = (size_t)row * Nout + col;
                float v0 = acc[mt][nt][2 * i2], v1 = acc[mt][nt][2 * i2 + 1];
                if (EPI == 0) {
                    *(float2*)&g_b[idx] = make_float2(v0, v1);
                    float u0 = RATEV * v0, u1 = RATEV * v1;
                    *(float2*)&g_u[idx] = make_float2(u0, u1);
                    float a0 = fmaxf(u0 - LAMV, 0.0f), a1 = fmaxf(u1 - LAMV, 0.0f);
                    *(__half2*)&g_ahi[idx] = __halves2half2(
                        __float2half_rn(a0), __float2half_rn(a1));
                } else {
                    *(float2*)&outp[idx] = make_float2(v0, v1);
                }
            }
        }
}

// ===================== 1-term GEMM (KC=64, 3-stage, SW128) =====================
// EPI 1: t     (A=ahi, B=Whi,  K=4096, Nout=1024): thi = fp16(C)
// EPI 3: u-upd (A=thi, B=Wthi, K=1024, Nout=4096): u update; ahi
template <int EPI>
__global__ __launch_bounds__(128, 2)
void lca_gemm1(float* __restrict__ outp)
{
    constexpr int Kdim = (EPI == 1) ? DLCA : DMODEL;
    constexpr int Nout = (EPI == 1) ? DMODEL : DLCA;
    constexpr int NC   = Kdim / KC1;

    const __half* Ahp = (EPI == 1) ? g_ahi : g_thi;
    const __half* Bhp = (EPI == 1) ? g_Whi : g_Wthi;

    extern __shared__ __align__(16) char smem[];
    const uint32_t sbase = smem_u32(smem);

    const int tid = threadIdx.x;
    const int wid = tid >> 5, l = tid & 31;
    const int wm = wid >> 1, wn = wid & 1;     // warp grid 2x2, tile 64x64
    const int mBase = blockIdx.y * 128;
    const int nBase = blockIdx.x * 128;

    const __half* Ah = Ahp + (size_t)mBase * Kdim;
    const __half* Bh = Bhp + (size_t)nBase * Kdim;

    auto load_stage = [&](int s, int k0) {
        uint32_t sb = sbase + s * STAGE1;
        #pragma unroll
        for (int i = 0; i < 8; i++) {
            int u = tid + i * 128;            // 0..1023
            int r = u >> 3, cc = u & 7;
            uint32_t so = r * ROWB1 + (cc ^ (r & 7)) * 16;
            size_t   go = (size_t)r * Kdim + k0 + cc * 8;
            CP_ASYNC(sb + so, Ah + go);
            CP_ASYNC(sb + T1_B + so, Bh + go);
        }
    };

    float acc[4][8][4];
    #pragma unroll
    for (int a = 0; a < 4; a++)
        #pragma unroll
        for (int b = 0; b < 8; b++)
            #pragma unroll
            for (int c = 0; c < 4; c++) acc[a][b][c] = 0.0f;

    const int rowA = wm * 64 + (l & 15);
    const uint32_t sA = (uint32_t)(rowA & 7);
    const uint32_t aRow = (uint32_t)rowA * ROWB1;
    const int colA0 = l >> 4;
    const int gB = l >> 3;
    const int rowB = wn * 64 + (l & 7) + (gB >> 1) * 8;
    const uint32_t sB = (uint32_t)(rowB & 7);
    const uint32_t bRow = (uint32_t)rowB * ROWB1;
    const int colB0 = gB & 1;

    load_stage(0, 0);   CP_COMMIT();
    load_stage(1, KC1); CP_COMMIT();

    for (int c = 0; c < NC; c++) {
        CP_WAIT1();
        __syncthreads();
        if (c + 2 < NC) load_stage((c + 2) % 3, (c + 2) * KC1);
        CP_COMMIT();

        uint32_t st = sbase + (c % 3) * STAGE1;
        #pragma unroll
        for (int k16 = 0; k16 < 4; k16++) {
            const uint32_t cA = (uint32_t)((colA0 + k16 * 2)) ^ sA;
            const uint32_t cB = (uint32_t)((colB0 + k16 * 2)) ^ sB;
            uint32_t aH = st + aRow + cA * 16;
            uint32_t bH = st + T1_B + bRow + cB * 16;
            uint32_t ah[4][4], bh[4][4];
            #pragma unroll
            for (int mt = 0; mt < 4; mt++) ldsm4(ah[mt], aH + mt * (16 * ROWB1));
            #pragma unroll
            for (int p = 0; p < 4; p++)    ldsm4(bh[p], bH + p * (16 * ROWB1));
            #pragma unroll
            for (int mt = 0; mt < 4; mt++)
                #pragma unroll
                for (int nt = 0; nt < 8; nt++)
                    mma16816(acc[mt][nt], ah[mt], &bh[nt >> 1][(nt & 1) * 2]);
        }
    }

    const int rb = wm * 64 + (l >> 2);
    const int cb = wn * 64 + 2 * (l & 3);
    #pragma unroll
    for (int mt = 0; mt < 4; mt++)
        #pragma unroll
        for (int i2 = 0; i2 < 2; i2++) {
            int row = mBase + rb + mt * 16 + i2 * 8;
            #pragma unroll
            for (int nt = 0; nt < 8; nt++) {
                int col = nBase + cb + nt * 8;
                size_t idx = (size_t)row * Nout + col;
                float v0 = acc[mt][nt][2 * i2], v1 = acc[mt][nt][2 * i2 + 1];
                if (EPI == 1) {
                    *(__half2*)&g_thi[idx] = __halves2half2(
                        __float2half_rn(v0), __float2half_rn(v1));
                } else {
                    float2 bb = *(float2*)&g_b[idx];
                    float2 uu = *(float2*)&g_u[idx];
                    float d0 = g_diag[col], d1 = g_diag[col + 1];
                    float ao0 = fmaxf(uu.x - LAMV, 0.0f), ao1 = fmaxf(uu.y - LAMV, 0.0f);
                    float aG0 = v0 - ao0 * d0, aG1 = v1 - ao1 * d1;
                    float un0 = uu.x + RATEV * (bb.x - aG0 - uu.x);
                    float un1 = uu.y + RATEV * (bb.y - aG1 - uu.y);
                    *(float2*)&g_u[idx] = make_float2(un0, un1);
                    float a0 = fmaxf(un0 - LAMV, 0.0f), a1 = fmaxf(un1 - LAMV, 0.0f);
                    *(__half2*)&g_ahi[idx] = __halves2half2(
                        __float2half_rn(a0), __float2half_rn(a1));
                }
            }
        }
}

// ---------------- launch ----------------
extern "C" void kernel_launch(void* const* d_in, const int* in_sizes, int n_in,
                              void* d_out, int out_size)
{
    const float* x = (const float*)d_in[0];
    const float* W = (const float*)d_in[1];
    if (n_in >= 2 && in_sizes[0] < in_sizes[1]) { const float* t = x; x = W; W = t; }
    float* out = (float*)d_out;

    cudaFuncSetAttribute(lca_gemm2t<0>, cudaFuncAttributeMaxDynamicSharedMemorySize, SMEM2T);
    cudaFuncSetAttribute(lca_gemm2t<2>, cudaFuncAttributeMaxDynamicSharedMemorySize, SMEM2T);
    cudaFuncSetAttribute(lca_gemm1<1>, cudaFuncAttributeMaxDynamicSharedMemorySize, SMEM1);
    cudaFuncSetAttribute(lca_gemm1<3>, cudaFuncAttributeMaxDynamicSharedMemorySize, SMEM1);

    split_x_kernel<<<(MDIM * DMODEL) / 256, 256>>>(x);
    splitW_kernel<<<dim3(DLCA / 32, DMODEL / 32), dim3(32, 8)>>>(W);
    diag_kernel<<<DLCA / 256, 256>>>(W);

    dim3 gridB(DLCA / 128, MDIM / 128);     // (32, 64)
    dim3 gridT(DMODEL / 128, MDIM / 128);   // (8, 64)

    lca_gemm2t<0><<<gridB, 128, SMEM2T>>>(nullptr);
    for (int s = 0; s < 9; s++) {
        lca_gemm1<1><<<gridT, 128, SMEM1>>>(nullptr);
        lca_gemm1<3><<<gridB, 128, SMEM1>>>(nullptr);
    }
    lca_gemm2t<2><<<gridT, 128, SMEM2T>>>(out);
}

// round 13
// speedup vs baseline: 1.0956x; 1.0956x over previous
#include <cuda_runtime.h>
#include <cuda_fp16.h>
#include <cstdint>

// LCA layer via mma.sync (HMMA), factored + precision-budgeted:
//   b = x@W (2-term) ; u1 = 0.1 b ; 9x { t = a@W^T (fp16) ; u-upd via tW (fp16) }
//   out = a@W^T (2-term)
// R13: 2-term kernels = R12 (128thr, 64x64 warp tile). 1-term kernels = R11
//      geometry (256thr, 64x32) + fragment double-buffering in the k16 loop.

#define MDIM   8192
#define DMODEL 1024
#define DLCA   4096
#define LAMV   0.1f
#define RATEV  0.1f

// ---- 2-term geometry (KC=32, 64B rows, swizzle c^((r>>1)&3)) ----
#define KC2    32
#define ROWB2  64
#define T2_B   (128 * ROWB2)         // 8192
#define STAGE2 (3 * T2_B)            // 24576
#define NST2   4
#define SMEM2T (NST2 * STAGE2)       // 98304

// ---- 1-term geometry (KC=64, 128B rows, SW128 c^(r&7)) ----
#define KC1    64
#define ROWB1  128
#define T1_B   (128 * ROWB1)         // 16384
#define STAGE1 (2 * T1_B)            // 32768
#define SMEM1  (3 * STAGE1)          // 98304

// fp32 state
__device__ __align__(16) float g_b[(size_t)MDIM * DLCA];
__device__ __align__(16) float g_u[(size_t)MDIM * DLCA];
__device__ float g_diag[DLCA];
// fp16 operands
__device__ __align__(16) __half g_ahi[(size_t)MDIM * DLCA];
__device__ __align__(16) __half g_thi[(size_t)MDIM * DMODEL];
__device__ __align__(16) __half g_xhi[(size_t)MDIM * DMODEL];
__device__ __align__(16) __half g_Whi[(size_t)DMODEL * DLCA];
__device__ __align__(16) __half g_Wlo[(size_t)DMODEL * DLCA];
__device__ __align__(16) __half g_Wthi[(size_t)DLCA * DMODEL];
__device__ __align__(16) __half g_Wtlo[(size_t)DLCA * DMODEL];

__device__ __forceinline__ uint32_t smem_u32(const void* p) {
    uint32_t a;
    asm("{ .reg .u64 t; cvta.to.shared.u64 t, %1; cvt.u32.u64 %0, t; }" : "=r"(a) : "l"(p));
    return a;
}
__device__ __forceinline__ void ldsm4(uint32_t r[4], uint32_t addr) {
    asm volatile("ldmatrix.sync.aligned.m8n8.x4.shared.b16 {%0,%1,%2,%3}, [%4];"
                 : "=r"(r[0]), "=r"(r[1]), "=r"(r[2]), "=r"(r[3]) : "r"(addr));
}
__device__ __forceinline__ void mma16816(float c[4], const uint32_t a[4], const uint32_t b[2]) {
    asm volatile("mma.sync.aligned.m16n8k16.row.col.f32.f16.f16.f32 "
                 "{%0,%1,%2,%3}, {%4,%5,%6,%7}, {%8,%9}, {%0,%1,%2,%3};"
                 : "+f"(c[0]), "+f"(c[1]), "+f"(c[2]), "+f"(c[3])
                 : "r"(a[0]), "r"(a[1]), "r"(a[2]), "r"(a[3]), "r"(b[0]), "r"(b[1]));
}
#define CP_ASYNC(dst, src) \
    asm volatile("cp.async.cg.shared.global [%0], [%1], 16;" :: "r"(dst), "l"(src) : "memory")
#define CP_COMMIT() asm volatile("cp.async.commit_group;" ::: "memory")
#define CP_WAIT1()  asm volatile("cp.async.wait_group 1;" ::: "memory")
#define CP_WAIT2()  asm volatile("cp.async.wait_group 2;" ::: "memory")

// ---------------- prep kernels ----------------
__global__ void split_x_kernel(const float* __restrict__ x) {
    size_t i = (size_t)blockIdx.x * blockDim.x + threadIdx.x;
    g_xhi[i] = __float2half_rn(x[i]);
}
__global__ void splitW_kernel(const float* __restrict__ W) {
    __shared__ float tile[32][33];
    int n0 = blockIdx.x * 32, k0 = blockIdx.y * 32;
    int tx = threadIdx.x, ty = threadIdx.y;
    #pragma unroll
    for (int r = 0; r < 4; r++) {
        int k = k0 + ty + r * 8;
        float v = W[(size_t)k * DLCA + n0 + tx];
        __half h = __float2half_rn(v);
        g_Whi[(size_t)k * DLCA + n0 + tx] = h;
        g_Wlo[(size_t)k * DLCA + n0 + tx] = __float2half_rn(v - __half2float(h));
        tile[ty + r * 8][tx] = v;
    }
    __syncthreads();
    #pragma unroll
    for (int r = 0; r < 4; r++) {
        int n = n0 + ty + r * 8;
        float v = tile[tx][ty + r * 8];
        __half h = __float2half_rn(v);
        g_Wthi[(size_t)n * DMODEL + k0 + tx] = h;
        g_Wtlo[(size_t)n * DMODEL + k0 + tx] = __float2half_rn(v - __half2float(h));
    }
}
__global__ void diag_kernel(const float* __restrict__ W) {
    int j = blockIdx.x * blockDim.x + threadIdx.x;
    float s = 0.0f;
    #pragma unroll 8
    for (int k = 0; k < DMODEL; k++) {
        float w = W[(size_t)k * DLCA + j];
        s = fmaf(w, w, s);
    }
    g_diag[j] = s;
}

// ===================== 2-term GEMM (KC=32, 4-stage, 128thr, 64x64 warp) ========
// D = Ah*(Bh + Bl).  EPI 0: b-init (A=xhi, B=Wt, K=1024, Nout=4096)
//                    EPI 2: out    (A=ahi, B=W,  K=4096, Nout=1024)
template <int EPI>
__global__ __launch_bounds__(128, 2)
void lca_gemm2t(float* __restrict__ outp)
{
    constexpr int Kdim = (EPI == 2) ? DLCA : DMODEL;
    constexpr int Nout = (EPI == 2) ? DMODEL : DLCA;
    constexpr int NC   = Kdim / KC2;

    const __half* Ahp = (EPI == 0) ? g_xhi : g_ahi;
    const __half* Bhp = (EPI == 2) ? g_Whi : g_Wthi;
    const __half* Blp = (EPI == 2) ? g_Wlo : g_Wtlo;

    extern __shared__ __align__(16) char smem[];
    const uint32_t sbase = smem_u32(smem);

    const int tid = threadIdx.x;
    const int wid = tid >> 5, l = tid & 31;
    const int wm = wid >> 1, wn = wid & 1;     // 2x2 warps, warp tile 64x64
    const int mBase = blockIdx.y * 128;
    const int nBase = blockIdx.x * 128;

    const __half* Ah = Ahp + (size_t)mBase * Kdim;
    const __half* Bh = Bhp + (size_t)nBase * Kdim;
    const __half* Bl = Blp + (size_t)nBase * Kdim;

    auto load_stage = [&](int s, int k0) {
        uint32_t sb = sbase + s * STAGE2;
        #pragma unroll
        for (int i = 0; i < 4; i++) {
            int u = tid + i * 128;
            int r = u >> 2, cc = u & 3;
            uint32_t so = r * ROWB2 + (cc ^ ((r >> 1) & 3)) * 16;
            size_t   go = (size_t)r * Kdim + k0 + cc * 8;
            CP_ASYNC(sb + so, Ah + go);
            CP_ASYNC(sb + T2_B + so, Bh + go);
            CP_ASYNC(sb + 2 * T2_B + so, Bl + go);
        }
    };

    float acc[4][8][4];
    #pragma unroll
    for (int a = 0; a < 4; a++)
        #pragma unroll
        for (int b = 0; b < 8; b++)
            #pragma unroll
            for (int c = 0; c < 4; c++) acc[a][b][c] = 0.0f;

    const int rowA = wm * 64 + (l & 15);
    const uint32_t sA = (uint32_t)((rowA >> 1) & 3);
    const uint32_t aRow = (uint32_t)rowA * ROWB2;
    const int colA0 = l >> 4;
    const int gB = l >> 3;
    const int rowB = wn * 64 + (l & 7) + (gB >> 1) * 8;
    const uint32_t sB = (uint32_t)((rowB >> 1) & 3);
    const uint32_t bRow = (uint32_t)rowB * ROWB2;
    const int colB0 = gB & 1;

    load_stage(0, 0);       CP_COMMIT();
    load_stage(1, KC2);     CP_COMMIT();
    load_stage(2, 2 * KC2); CP_COMMIT();

    for (int c = 0; c < NC; c++) {
        CP_WAIT2();
        __syncthreads();
        if (c + 3 < NC) load_stage((c + 3) % NST2, (c + 3) * KC2);
        CP_COMMIT();

        uint32_t st = sbase + (c % NST2) * STAGE2;
        #pragma unroll
        for (int k16 = 0; k16 < 2; k16++) {
            const uint32_t cA = (uint32_t)((colA0 + k16 * 2)) ^ sA;
            const uint32_t cB = (uint32_t)((colB0 + k16 * 2)) ^ sB;
            uint32_t aH = st + aRow + cA * 16;
            uint32_t bH = st + T2_B + bRow + cB * 16;
            uint32_t bL = st + 2 * T2_B + bRow + cB * 16;
            uint32_t ah[4][4], bh[4][4], bl[4][4];
            #pragma unroll
            for (int mt = 0; mt < 4; mt++) ldsm4(ah[mt], aH + mt * (16 * ROWB2));
            #pragma unroll
            for (int p = 0; p < 4; p++)    ldsm4(bh[p], bH + p * (16 * ROWB2));
            #pragma unroll
            for (int mt = 0; mt < 4; mt++)
                #pragma unroll
                for (int nt = 0; nt < 8; nt++)
                    mma16816(acc[mt][nt], ah[mt], &bh[nt >> 1][(nt & 1) * 2]);
            #pragma unroll
            for (int p = 0; p < 4; p++)    ldsm4(bl[p], bL + p * (16 * ROWB2));
            #pragma unroll
            for (int mt = 0; mt < 4; mt++)
                #pragma unroll
                for (int nt = 0; nt < 8; nt++)
                    mma16816(acc[mt][nt], ah[mt], &bl[nt >> 1][(nt & 1) * 2]);
        }
    }

    const int rb = wm * 64 + (l >> 2);
    const int cb = wn * 64 + 2 * (l & 3);
    #pragma unroll
    for (int mt = 0; mt < 4; mt++)
        #pragma unroll
        for (int i2 = 0; i2 < 2; i2++) {
            int row = mBase + rb + mt * 16 + i2 * 8;
            #pragma unroll
            for (int nt = 0; nt < 8; nt++) {
                int col = nBase + cb + nt * 8;
                size_t idx = (size_t)row * Nout + col;
                float v0 = acc[mt][nt][2 * i2], v1 = acc[mt][nt][2 * i2 + 1];
                if (EPI == 0) {
                    *(float2*)&g_b[idx] = make_float2(v0, v1);
                    float u0 = RATEV * v0, u1 = RATEV * v1;
                    *(float2*)&g_u[idx] = make_float2(u0, u1);
                    float a0 = fmaxf(u0 - LAMV, 0.0f), a1 = fmaxf(u1 - LAMV, 0.0f);
                    *(__half2*)&g_ahi[idx] = __halves2half2(
                        __float2half_rn(a0), __float2half_rn(a1));
                } else {
                    *(float2*)&outp[idx] = make_float2(v0, v1);
                }
            }
        }
}

// ========== 1-term GEMM (KC=64, 3-stage, 256thr, 64x32 warp, frag pipeline) ====
// EPI 1: t     (A=ahi, B=Whi,  K=4096, Nout=1024): thi = fp16(C)
// EPI 3: u-upd (A=thi, B=Wthi, K=1024, Nout=4096): u update; ahi
template <int EPI>
__global__ __launch_bounds__(256, 2)
void lca_gemm1(float* __restrict__ outp)
{
    constexpr int Kdim = (EPI == 1) ? DLCA : DMODEL;
    constexpr int Nout = (EPI == 1) ? DMODEL : DLCA;
    constexpr int NC   = Kdim / KC1;

    const __half* Ahp = (EPI == 1) ? g_ahi : g_thi;
    const __half* Bhp = (EPI == 1) ? g_Whi : g_Wthi;

    extern __shared__ __align__(16) char smem[];
    const uint32_t sbase = smem_u32(smem);

    const int tid = threadIdx.x;
    const int wid = tid >> 5, l = tid & 31;
    const int wm = wid >> 2, wn = wid & 3;     // 4x4 warps, warp tile 64x32
    const int mBase = blockIdx.y * 128;
    const int nBase = blockIdx.x * 128;

    const __half* Ah = Ahp + (size_t)mBase * Kdim;
    const __half* Bh = Bhp + (size_t)nBase * Kdim;

    auto load_stage = [&](int s, int k0) {
        uint32_t sb = sbase + s * STAGE1;
        #pragma unroll
        for (int i = 0; i < 4; i++) {
            int u = tid + i * 256;
            int r = u >> 3, cc = u & 7;
            uint32_t so = r * ROWB1 + (cc ^ (r & 7)) * 16;
            size_t   go = (size_t)r * Kdim + k0 + cc * 8;
            CP_ASYNC(sb + so, Ah + go);
            CP_ASYNC(sb + T1_B + so, Bh + go);
        }
    };

    float acc[4][4][4];
    #pragma unroll
    for (int a = 0; a < 4; a++)
        #pragma unroll
        for (int b = 0; b < 4; b++)
            #pragma unroll
            for (int c = 0; c < 4; c++) acc[a][b][c] = 0.0f;

    const int rowA = wm * 64 + (l & 15);
    const uint32_t sA = (uint32_t)(rowA & 7);
    const uint32_t aRow = (uint32_t)rowA * ROWB1;
    const int colA0 = l >> 4;
    const int gB = l >> 3;
    const int rowB = wn * 32 + (l & 7) + (gB >> 1) * 8;
    const uint32_t sB = (uint32_t)(rowB & 7);
    const uint32_t bRow = (uint32_t)rowB * ROWB1;
    const int colB0 = gB & 1;

    auto ldA = [&](uint32_t st, int k16, uint32_t dst[4][4]) {
        uint32_t cA = (uint32_t)((colA0 + k16 * 2)) ^ sA;
        uint32_t aH = st + aRow + cA * 16;
        #pragma unroll
        for (int mt = 0; mt < 4; mt++) ldsm4(dst[mt], aH + mt * (16 * ROWB1));
    };
    auto ldB = [&](uint32_t st, int k16, uint32_t dst[2][4]) {
        uint32_t cB = (uint32_t)((colB0 + k16 * 2)) ^ sB;
        uint32_t bH = st + T1_B + bRow + cB * 16;
        #pragma unroll
        for (int p = 0; p < 2; p++) ldsm4(dst[p], bH + p * (16 * ROWB1));
    };

    load_stage(0, 0);   CP_COMMIT();
    load_stage(1, KC1); CP_COMMIT();

    uint32_t ahf[2][4][4], bhf[2][2][4];

    for (int c = 0; c < NC; c++) {
        CP_WAIT1();
        __syncthreads();
        if (c + 2 < NC) load_stage((c + 2) % 3, (c + 2) * KC1);
        CP_COMMIT();

        uint32_t st = sbase + (c % 3) * STAGE1;
        ldA(st, 0, ahf[0]);
        ldB(st, 0, bhf[0]);
        #pragma unroll
        for (int k16 = 0; k16 < 4; k16++) {
            int cur = k16 & 1, nxt = cur ^ 1;
            if (k16 < 3) { ldA(st, k16 + 1, ahf[nxt]); ldB(st, k16 + 1, bhf[nxt]); }
            #pragma unroll
            for (int mt = 0; mt < 4; mt++)
                #pragma unroll
                for (int nt = 0; nt < 4; nt++)
                    mma16816(acc[mt][nt], ahf[cur][mt], &bhf[cur][nt >> 1][(nt & 1) * 2]);
        }
    }

    const int rb = wm * 64 + (l >> 2);
    const int cb = wn * 32 + 2 * (l & 3);
    #pragma unroll
    for (int mt = 0; mt < 4; mt++)
        #pragma unroll
        for (int i2 = 0; i2 < 2; i2++) {
            int row = mBase + rb + mt * 16 + i2 * 8;
            #pragma unroll
            for (int nt = 0; nt < 4; nt++) {
                int col = nBase + cb + nt * 8;
                size_t idx = (size_t)row * Nout + col;
                float v0 = acc[mt][nt][2 * i2], v1 = acc[mt][nt][2 * i2 + 1];
                if (EPI == 1) {
                    *(__half2*)&g_thi[idx] = __halves2half2(
                        __float2half_rn(v0), __float2half_rn(v1));
                } else {
                    float2 bb = *(float2*)&g_b[idx];
                    float2 uu = *(float2*)&g_u[idx];
                    float d0 = g_diag[col], d1 = g_diag[col + 1];
                    float ao0 = fmaxf(uu.x - LAMV, 0.0f), ao1 = fmaxf(uu.y - LAMV, 0.0f);
                    float aG0 = v0 - ao0 * d0, aG1 = v1 - ao1 * d1;
                    float un0 = uu.x + RATEV * (bb.x - aG0 - uu.x);
                    float un1 = uu.y + RATEV * (bb.y - aG1 - uu.y);
                    *(float2*)&g_u[idx] = make_float2(un0, un1);
                    float a0 = fmaxf(un0 - LAMV, 0.0f), a1 = fmaxf(un1 - LAMV, 0.0f);
                    *(__half2*)&g_ahi[idx] = __halves2half2(
                        __float2half_rn(a0), __float2half_rn(a1));
                }
            }
        }
}

// ---------------- launch ----------------
extern "C" void kernel_launch(void* const* d_in, const int* in_sizes, int n_in,
                              void* d_out, int out_size)
{
    const float* x = (const float*)d_in[0];
    const float* W = (const float*)d_in[1];
    if (n_in >= 2 && in_sizes[0] < in_sizes[1]) { const float* t = x; x = W; W = t; }
    float* out = (float*)d_out;

    cudaFuncSetAttribute(lca_gemm2t<0>, cudaFuncAttributeMaxDynamicSharedMemorySize, SMEM2T);
    cudaFuncSetAttribute(lca_gemm2t<2>, cudaFuncAttributeMaxDynamicSharedMemorySize, SMEM2T);
    cudaFuncSetAttribute(lca_gemm1<1>, cudaFuncAttributeMaxDynamicSharedMemorySize, SMEM1);
    cudaFuncSetAttribute(lca_gemm1<3>, cudaFuncAttributeMaxDynamicSharedMemorySize, SMEM1);

    split_x_kernel<<<(MDIM * DMODEL) / 256, 256>>>(x);
    splitW_kernel<<<dim3(DLCA / 32, DMODEL / 32), dim3(32, 8)>>>(W);
    diag_kernel<<<DLCA / 256, 256>>>(W);

    dim3 gridB(DLCA / 128, MDIM / 128);     // (32, 64)
    dim3 gridT(DMODEL / 128, MDIM / 128);   // (8, 64)

    lca_gemm2t<0><<<gridB, 128, SMEM2T>>>(nullptr);
    for (int s = 0; s < 9; s++) {
        lca_gemm1<1><<<gridT, 256, SMEM1>>>(nullptr);
        lca_gemm1<3><<<gridB, 256, SMEM1>>>(nullptr);
    }
    lca_gemm2t<2><<<gridT, 128, SMEM2T>>>(out);
}

// round 14
// speedup vs baseline: 1.1876x; 1.0839x over previous
#include <cuda_runtime.h>
#include <cuda_fp16.h>
#include <cstdint>

// LCA layer via mma.sync (HMMA), factored + precision-budgeted:
//   b = x@W (2-term) ; u1 = 0.1 b ; 9x { t = a@W^T (fp16) ; u-upd via tW (fp16) }
//   out = a@W^T (2-term)
// R14: 2-term = R12 form (128thr, 64x64 warp). EPI3 = R11 form (256thr, 64x32).
//      EPI1 re-tiled 64x128 / 128thr / 3 CTAs/SM for wave packing (1024 CTAs
//      over 444 slots = 1.5T vs 2.0T).

#define MDIM   8192
#define DMODEL 1024
#define DLCA   4096
#define LAMV   0.1f
#define RATEV  0.1f

// ---- 2-term geometry (KC=32, 64B rows, swizzle c^((r>>1)&3)) ----
#define KC2    32
#define ROWB2  64
#define T2_B   (128 * ROWB2)         // 8192
#define STAGE2 (3 * T2_B)            // 24576
#define NST2   4
#define SMEM2T (NST2 * STAGE2)       // 98304

// ---- EPI3 1-term geometry (KC=64, 128B rows, SW128) ----
#define KC1    64
#define ROWB1  128
#define T1_B   (128 * ROWB1)         // 16384
#define STAGE1 (2 * T1_B)            // 32768
#define SMEM1  (3 * STAGE1)          // 98304

// ---- EPI1 1-term geometry (tile 64x128, KC=64, 128B rows, SW128) ----
#define TE_A   (64 * ROWB1)          // 8192
#define TE_B   (128 * ROWB1)         // 16384
#define STAGEE (TE_A + TE_B)         // 24576
#define SMEME  (3 * STAGEE)          // 73728

// fp32 state
__device__ __align__(16) float g_b[(size_t)MDIM * DLCA];
__device__ __align__(16) float g_u[(size_t)MDIM * DLCA];
__device__ float g_diag[DLCA];
// fp16 operands
__device__ __align__(16) __half g_ahi[(size_t)MDIM * DLCA];
__device__ __align__(16) __half g_thi[(size_t)MDIM * DMODEL];
__device__ __align__(16) __half g_xhi[(size_t)MDIM * DMODEL];
__device__ __align__(16) __half g_Whi[(size_t)DMODEL * DLCA];
__device__ __align__(16) __half g_Wlo[(size_t)DMODEL * DLCA];
__device__ __align__(16) __half g_Wthi[(size_t)DLCA * DMODEL];
__device__ __align__(16) __half g_Wtlo[(size_t)DLCA * DMODEL];

__device__ __forceinline__ uint32_t smem_u32(const void* p) {
    uint32_t a;
    asm("{ .reg .u64 t; cvta.to.shared.u64 t, %1; cvt.u32.u64 %0, t; }" : "=r"(a) : "l"(p));
    return a;
}
__device__ __forceinline__ void ldsm4(uint32_t r[4], uint32_t addr) {
    asm volatile("ldmatrix.sync.aligned.m8n8.x4.shared.b16 {%0,%1,%2,%3}, [%4];"
                 : "=r"(r[0]), "=r"(r[1]), "=r"(r[2]), "=r"(r[3]) : "r"(addr));
}
__device__ __forceinline__ void mma16816(float c[4], const uint32_t a[4], const uint32_t b[2]) {
    asm volatile("mma.sync.aligned.m16n8k16.row.col.f32.f16.f16.f32 "
                 "{%0,%1,%2,%3}, {%4,%5,%6,%7}, {%8,%9}, {%0,%1,%2,%3};"
                 : "+f"(c[0]), "+f"(c[1]), "+f"(c[2]), "+f"(c[3])
                 : "r"(a[0]), "r"(a[1]), "r"(a[2]), "r"(a[3]), "r"(b[0]), "r"(b[1]));
}
#define CP_ASYNC(dst, src) \
    asm volatile("cp.async.cg.shared.global [%0], [%1], 16;" :: "r"(dst), "l"(src) : "memory")
#define CP_COMMIT() asm volatile("cp.async.commit_group;" ::: "memory")
#define CP_WAIT1()  asm volatile("cp.async.wait_group 1;" ::: "memory")
#define CP_WAIT2()  asm volatile("cp.async.wait_group 2;" ::: "memory")

// ---------------- prep kernels ----------------
__global__ void split_x_kernel(const float* __restrict__ x) {
    size_t i = (size_t)blockIdx.x * blockDim.x + threadIdx.x;
    g_xhi[i] = __float2half_rn(x[i]);
}
__global__ void splitW_kernel(const float* __restrict__ W) {
    __shared__ float tile[32][33];
    int n0 = blockIdx.x * 32, k0 = blockIdx.y * 32;
    int tx = threadIdx.x, ty = threadIdx.y;
    #pragma unroll
    for (int r = 0; r < 4; r++) {
        int k = k0 + ty + r * 8;
        float v = W[(size_t)k * DLCA + n0 + tx];
        __half h = __float2half_rn(v);
        g_Whi[(size_t)k * DLCA + n0 + tx] = h;
        g_Wlo[(size_t)k * DLCA + n0 + tx] = __float2half_rn(v - __half2float(h));
        tile[ty + r * 8][tx] = v;
    }
    __syncthreads();
    #pragma unroll
    for (int r = 0; r < 4; r++) {
        int n = n0 + ty + r * 8;
        float v = tile[tx][ty + r * 8];
        __half h = __float2half_rn(v);
        g_Wthi[(size_t)n * DMODEL + k0 + tx] = h;
        g_Wtlo[(size_t)n * DMODEL + k0 + tx] = __float2half_rn(v - __half2float(h));
    }
}
__global__ void diag_kernel(const float* __restrict__ W) {
    int j = blockIdx.x * blockDim.x + threadIdx.x;
    float s = 0.0f;
    #pragma unroll 8
    for (int k = 0; k < DMODEL; k++) {
        float w = W[(size_t)k * DLCA + j];
        s = fmaf(w, w, s);
    }
    g_diag[j] = s;
}

// ===================== 2-term GEMM (KC=32, 4-stage, 128thr, 64x64 warp) ========
template <int EPI>
__global__ __launch_bounds__(128, 2)
void lca_gemm2t(float* __restrict__ outp)
{
    constexpr int Kdim = (EPI == 2) ? DLCA : DMODEL;
    constexpr int Nout = (EPI == 2) ? DMODEL : DLCA;
    constexpr int NC   = Kdim / KC2;

    const __half* Ahp = (EPI == 0) ? g_xhi : g_ahi;
    const __half* Bhp = (EPI == 2) ? g_Whi : g_Wthi;
    const __half* Blp = (EPI == 2) ? g_Wlo : g_Wtlo;

    extern __shared__ __align__(16) char smem[];
    const uint32_t sbase = smem_u32(smem);

    const int tid = threadIdx.x;
    const int wid = tid >> 5, l = tid & 31;
    const int wm = wid >> 1, wn = wid & 1;
    const int mBase = blockIdx.y * 128;
    const int nBase = blockIdx.x * 128;

    const __half* Ah = Ahp + (size_t)mBase * Kdim;
    const __half* Bh = Bhp + (size_t)nBase * Kdim;
    const __half* Bl = Blp + (size_t)nBase * Kdim;

    auto load_stage = [&](int s, int k0) {
        uint32_t sb = sbase + s * STAGE2;
        #pragma unroll
        for (int i = 0; i < 4; i++) {
            int u = tid + i * 128;
            int r = u >> 2, cc = u & 3;
            uint32_t so = r * ROWB2 + (cc ^ ((r >> 1) & 3)) * 16;
            size_t   go = (size_t)r * Kdim + k0 + cc * 8;
            CP_ASYNC(sb + so, Ah + go);
            CP_ASYNC(sb + T2_B + so, Bh + go);
            CP_ASYNC(sb + 2 * T2_B + so, Bl + go);
        }
    };

    float acc[4][8][4];
    #pragma unroll
    for (int a = 0; a < 4; a++)
        #pragma unroll
        for (int b = 0; b < 8; b++)
            #pragma unroll
            for (int c = 0; c < 4; c++) acc[a][b][c] = 0.0f;

    const int rowA = wm * 64 + (l & 15);
    const uint32_t sA = (uint32_t)((rowA >> 1) & 3);
    const uint32_t aRow = (uint32_t)rowA * ROWB2;
    const int colA0 = l >> 4;
    const int gB = l >> 3;
    const int rowB = wn * 64 + (l & 7) + (gB >> 1) * 8;
    const uint32_t sB = (uint32_t)((rowB >> 1) & 3);
    const uint32_t bRow = (uint32_t)rowB * ROWB2;
    const int colB0 = gB & 1;

    load_stage(0, 0);       CP_COMMIT();
    load_stage(1, KC2);     CP_COMMIT();
    load_stage(2, 2 * KC2); CP_COMMIT();

    for (int c = 0; c < NC; c++) {
        CP_WAIT2();
        __syncthreads();
        if (c + 3 < NC) load_stage((c + 3) % NST2, (c + 3) * KC2);
        CP_COMMIT();

        uint32_t st = sbase + (c % NST2) * STAGE2;
        #pragma unroll
        for (int k16 = 0; k16 < 2; k16++) {
            const uint32_t cA = (uint32_t)((colA0 + k16 * 2)) ^ sA;
            const uint32_t cB = (uint32_t)((colB0 + k16 * 2)) ^ sB;
            uint32_t aH = st + aRow + cA * 16;
            uint32_t bH = st + T2_B + bRow + cB * 16;
            uint32_t bL = st + 2 * T2_B + bRow + cB * 16;
            uint32_t ah[4][4], bh[4][4], bl[4][4];
            #pragma unroll
            for (int mt = 0; mt < 4; mt++) ldsm4(ah[mt], aH + mt * (16 * ROWB2));
            #pragma unroll
            for (int p = 0; p < 4; p++)    ldsm4(bh[p], bH + p * (16 * ROWB2));
            #pragma unroll
            for (int mt = 0; mt < 4; mt++)
                #pragma unroll
                for (int nt = 0; nt < 8; nt++)
                    mma16816(acc[mt][nt], ah[mt], &bh[nt >> 1][(nt & 1) * 2]);
            #pragma unroll
            for (int p = 0; p < 4; p++)    ldsm4(bl[p], bL + p * (16 * ROWB2));
            #pragma unroll
            for (int mt = 0; mt < 4; mt++)
                #pragma unroll
                for (int nt = 0; nt < 8; nt++)
                    mma16816(acc[mt][nt], ah[mt], &bl[nt >> 1][(nt & 1) * 2]);
        }
    }

    const int rb = wm * 64 + (l >> 2);
    const int cb = wn * 64 + 2 * (l & 3);
    #pragma unroll
    for (int mt = 0; mt < 4; mt++)
        #pragma unroll
        for (int i2 = 0; i2 < 2; i2++) {
            int row = mBase + rb + mt * 16 + i2 * 8;
            #pragma unroll
            for (int nt = 0; nt < 8; nt++) {
                int col = nBase + cb + nt * 8;
                size_t idx = (size_t)row * Nout + col;
                float v0 = acc[mt][nt][2 * i2], v1 = acc[mt][nt][2 * i2 + 1];
                if (EPI == 0) {
                    *(float2*)&g_b[idx] = make_float2(v0, v1);
                    float u0 = RATEV * v0, u1 = RATEV * v1;
                    *(float2*)&g_u[idx] = make_float2(u0, u1);
                    float a0 = fmaxf(u0 - LAMV, 0.0f), a1 = fmaxf(u1 - LAMV, 0.0f);
                    *(__half2*)&g_ahi[idx] = __halves2half2(
                        __float2half_rn(a0), __float2half_rn(a1));
                } else {
                    *(float2*)&outp[idx] = make_float2(v0, v1);
                }
            }
        }
}

// ========== EPI3: u-update 1-term GEMM (R11 form: 256thr, 64x32 warp) ==========
// (A=thi, B=Wthi, K=1024, Nout=4096)
__global__ __launch_bounds__(256, 2)
void lca_gemm_upd()
{
    constexpr int Kdim = DMODEL;
    constexpr int Nout = DLCA;
    constexpr int NC   = Kdim / KC1;

    extern __shared__ __align__(16) char smem[];
    const uint32_t sbase = smem_u32(smem);

    const int tid = threadIdx.x;
    const int wid = tid >> 5, l = tid & 31;
    const int wm = wid >> 2, wn = wid & 3;
    const int mBase = blockIdx.y * 128;
    const int nBase = blockIdx.x * 128;

    const __half* Ah = g_thi + (size_t)mBase * Kdim;
    const __half* Bh = g_Wthi + (size_t)nBase * Kdim;

    auto load_stage = [&](int s, int k0) {
        uint32_t sb = sbase + s * STAGE1;
        #pragma unroll
        for (int i = 0; i < 4; i++) {
            int u = tid + i * 256;
            int r = u >> 3, cc = u & 7;
            uint32_t so = r * ROWB1 + (cc ^ (r & 7)) * 16;
            size_t   go = (size_t)r * Kdim + k0 + cc * 8;
            CP_ASYNC(sb + so, Ah + go);
            CP_ASYNC(sb + T1_B + so, Bh + go);
        }
    };

    float acc[4][4][4];
    #pragma unroll
    for (int a = 0; a < 4; a++)
        #pragma unroll
        for (int b = 0; b < 4; b++)
            #pragma unroll
            for (int c = 0; c < 4; c++) acc[a][b][c] = 0.0f;

    const int rowA = wm * 64 + (l & 15);
    const uint32_t sA = (uint32_t)(rowA & 7);
    const uint32_t aRow = (uint32_t)rowA * ROWB1;
    const int colA0 = l >> 4;
    const int gB = l >> 3;
    const int rowB = wn * 32 + (l & 7) + (gB >> 1) * 8;
    const uint32_t sB = (uint32_t)(rowB & 7);
    const uint32_t bRow = (uint32_t)rowB * ROWB1;
    const int colB0 = gB & 1;

    load_stage(0, 0);   CP_COMMIT();
    load_stage(1, KC1); CP_COMMIT();

    for (int c = 0; c < NC; c++) {
        CP_WAIT1();
        __syncthreads();
        if (c + 2 < NC) load_stage((c + 2) % 3, (c + 2) * KC1);
        CP_COMMIT();

        uint32_t st = sbase + (c % 3) * STAGE1;
        #pragma unroll
        for (int k16 = 0; k16 < 4; k16++) {
            const uint32_t cA = (uint32_t)((colA0 + k16 * 2)) ^ sA;
            const uint32_t cB = (uint32_t)((colB0 + k16 * 2)) ^ sB;
            uint32_t aH = st + aRow + cA * 16;
            uint32_t bH = st + T1_B + bRow + cB * 16;
            uint32_t ah[4][4], bh[2][4];
            #pragma unroll
            for (int mt = 0; mt < 4; mt++) ldsm4(ah[mt], aH + mt * (16 * ROWB1));
            #pragma unroll
            for (int p = 0; p < 2; p++)    ldsm4(bh[p], bH + p * (16 * ROWB1));
            #pragma unroll
            for (int mt = 0; mt < 4; mt++)
                #pragma unroll
                for (int nt = 0; nt < 4; nt++)
                    mma16816(acc[mt][nt], ah[mt], &bh[nt >> 1][(nt & 1) * 2]);
        }
    }

    const int rb = wm * 64 + (l >> 2);
    const int cb = wn * 32 + 2 * (l & 3);
    #pragma unroll
    for (int mt = 0; mt < 4; mt++)
        #pragma unroll
        for (int i2 = 0; i2 < 2; i2++) {
            int row = mBase + rb + mt * 16 + i2 * 8;
            #pragma unroll
            for (int nt = 0; nt < 4; nt++) {
                int col = nBase + cb + nt * 8;
                size_t idx = (size_t)row * Nout + col;
                float v0 = acc[mt][nt][2 * i2], v1 = acc[mt][nt][2 * i2 + 1];
                float2 bb = *(float2*)&g_b[idx];
                float2 uu = *(float2*)&g_u[idx];
                float d0 = g_diag[col], d1 = g_diag[col + 1];
                float ao0 = fmaxf(uu.x - LAMV, 0.0f), ao1 = fmaxf(uu.y - LAMV, 0.0f);
                float aG0 = v0 - ao0 * d0, aG1 = v1 - ao1 * d1;
                float un0 = uu.x + RATEV * (bb.x - aG0 - uu.x);
                float un1 = uu.y + RATEV * (bb.y - aG1 - uu.y);
                *(float2*)&g_u[idx] = make_float2(un0, un1);
                float a0 = fmaxf(un0 - LAMV, 0.0f), a1 = fmaxf(un1 - LAMV, 0.0f);
                *(__half2*)&g_ahi[idx] = __halves2half2(
                    __float2half_rn(a0), __float2half_rn(a1));
            }
        }
}

// ========== EPI1: t GEMM, tile 64x128, 128thr, 3 CTAs/SM ==========
// (A=ahi, B=Whi, K=4096, Nout=1024): thi = fp16(C)
__global__ __launch_bounds__(128, 3)
void lca_gemm_t()
{
    constexpr int Kdim = DLCA;
    constexpr int Nout = DMODEL;
    constexpr int NC   = Kdim / KC1;

    extern __shared__ __align__(16) char smem[];
    const uint32_t sbase = smem_u32(smem);

    const int tid = threadIdx.x;
    const int wid = tid >> 5, l = tid & 31;     // 4 warps, 1(m) x 4(n), warp tile 64x32
    const int wn = wid;
    const int mBase = blockIdx.y * 64;
    const int nBase = blockIdx.x * 128;

    const __half* Ah = g_ahi + (size_t)mBase * Kdim;
    const __half* Bh = g_Whi + (size_t)nBase * Kdim;

    // stage: [A 64r x 128B][B 128r x 128B], SW128
    auto load_stage = [&](int s, int k0) {
        uint32_t sb = sbase + s * STAGEE;
        #pragma unroll
        for (int i = 0; i < 4; i++) {           // A: 512 units
            int u = tid + i * 128;
            int r = u >> 3, cc = u & 7;
            uint32_t so = r * ROWB1 + (cc ^ (r & 7)) * 16;
            CP_ASYNC(sb + so, Ah + (size_t)r * Kdim + k0 + cc * 8);
        }
        #pragma unroll
        for (int i = 0; i < 8; i++) {           // B: 1024 units
            int u = tid + i * 128;
            int r = u >> 3, cc = u & 7;
            uint32_t so = r * ROWB1 + (cc ^ (r & 7)) * 16;
            CP_ASYNC(sb + TE_A + so, Bh + (size_t)r * Kdim + k0 + cc * 8);
        }
    };

    float acc[4][4][4];
    #pragma unroll
    for (int a = 0; a < 4; a++)
        #pragma unroll
        for (int b = 0; b < 4; b++)
            #pragma unroll
            for (int c = 0; c < 4; c++) acc[a][b][c] = 0.0f;

    const int rowA = l & 15;
    const uint32_t sA = (uint32_t)(rowA & 7);
    const uint32_t aRow = (uint32_t)rowA * ROWB1;
    const int colA0 = l >> 4;
    const int gB = l >> 3;
    const int rowB = wn * 32 + (l & 7) + (gB >> 1) * 8;
    const uint32_t sB = (uint32_t)(rowB & 7);
    const uint32_t bRow = (uint32_t)rowB * ROWB1;
    const int colB0 = gB & 1;

    load_stage(0, 0);   CP_COMMIT();
    load_stage(1, KC1); CP_COMMIT();

    for (int c = 0; c < NC; c++) {
        CP_WAIT1();
        __syncthreads();
        if (c + 2 < NC) load_stage((c + 2) % 3, (c + 2) * KC1);
        CP_COMMIT();

        uint32_t st = sbase + (c % 3) * STAGEE;
        #pragma unroll
        for (int k16 = 0; k16 < 4; k16++) {
            const uint32_t cA = (uint32_t)((colA0 + k16 * 2)) ^ sA;
            const uint32_t cB = (uint32_t)((colB0 + k16 * 2)) ^ sB;
            uint32_t aH = st + aRow + cA * 16;
            uint32_t bH = st + TE_A + bRow + cB * 16;
            uint32_t ah[4][4], bh[2][4];
            #pragma unroll
            for (int mt = 0; mt < 4; mt++) ldsm4(ah[mt], aH + mt * (16 * ROWB1));
            #pragma unroll
            for (int p = 0; p < 2; p++)    ldsm4(bh[p], bH + p * (16 * ROWB1));
            #pragma unroll
            for (int mt = 0; mt < 4; mt++)
                #pragma unroll
                for (int nt = 0; nt < 4; nt++)
                    mma16816(acc[mt][nt], ah[mt], &bh[nt >> 1][(nt & 1) * 2]);
        }
    }

    const int rb = l >> 2;
    const int cb = wn * 32 + 2 * (l & 3);
    #pragma unroll
    for (int mt = 0; mt < 4; mt++)
        #pragma unroll
        for (int i2 = 0; i2 < 2; i2++) {
            int row = mBase + rb + mt * 16 + i2 * 8;
            #pragma unroll
            for (int nt = 0; nt < 4; nt++) {
                int col = nBase + cb + nt * 8;
                size_t idx = (size_t)row * Nout + col;
                *(__half2*)&g_thi[idx] = __halves2half2(
                    __float2half_rn(acc[mt][nt][2 * i2]),
                    __float2half_rn(acc[mt][nt][2 * i2 + 1]));
            }
        }
}

// ---------------- launch ----------------
extern "C" void kernel_launch(void* const* d_in, const int* in_sizes, int n_in,
                              void* d_out, int out_size)
{
    const float* x = (const float*)d_in[0];
    const float* W = (const float*)d_in[1];
    if (n_in >= 2 && in_sizes[0] < in_sizes[1]) { const float* t = x; x = W; W = t; }
    float* out = (float*)d_out;

    cudaFuncSetAttribute(lca_gemm2t<0>, cudaFuncAttributeMaxDynamicSharedMemorySize, SMEM2T);
    cudaFuncSetAttribute(lca_gemm2t<2>, cudaFuncAttributeMaxDynamicSharedMemorySize, SMEM2T);
    cudaFuncSetAttribute(lca_gemm_upd, cudaFuncAttributeMaxDynamicSharedMemorySize, SMEM1);
    cudaFuncSetAttribute(lca_gemm_t,   cudaFuncAttributeMaxDynamicSharedMemorySize, SMEME);

    split_x_kernel<<<(MDIM * DMODEL) / 256, 256>>>(x);
    splitW_kernel<<<dim3(DLCA / 32, DMODEL / 32), dim3(32, 8)>>>(W);
    diag_kernel<<<DLCA / 256, 256>>>(W);

    dim3 gridB(DLCA / 128, MDIM / 128);     // (32, 64)
    dim3 gridT2(DMODEL / 128, MDIM / 128);  // (8, 64)
    dim3 gridT(DMODEL / 128, MDIM / 64);    // (8, 128) = 1024 CTAs

    lca_gemm2t<0><<<gridB, 128, SMEM2T>>>(nullptr);
    for (int s = 0; s < 9; s++) {
        lca_gemm_t<<<gridT, 128, SMEME>>>();
        lca_gemm_upd<<<gridB, 256, SMEM1>>>();
    }
    lca_gemm2t<2><<<gridT2, 128, SMEM2T>>>(out);
}

// round 15
// speedup vs baseline: 1.1885x; 1.0008x over previous
#include <cuda_runtime.h>
#include <cuda_fp16.h>
#include <cstdint>

// LCA layer via mma.sync (HMMA), factored + precision-budgeted:
//   b = x@W (2-term) ; u1 = 0.1 b ; 9x { t = a@W^T (fp16) ; u-upd via tW (fp16) }
//   out = a@W^T (2-term)
// R15: EPI2 re-tiled 64x128 / 3 CTAs/SM (wave packing, like R14's EPI1 fix).
//      b stored fp16 (read-weight 0.1 in the update -> ~2.5e-4 extra error).

#define MDIM   8192
#define DMODEL 1024
#define DLCA   4096
#define LAMV   0.1f
#define RATEV  0.1f

// ---- 2-term 128x128 geometry (EPI0): KC=32, 64B rows ----
#define KC2    32
#define ROWB2  64
#define T2_B   (128 * ROWB2)         // 8192
#define STAGE2 (3 * T2_B)            // 24576
#define NST2   4
#define SMEM2T (NST2 * STAGE2)       // 98304

// ---- EPI2 2-term 64x128 geometry: KC=32, 64B rows, 3-stage, 3 CTAs/SM ----
#define TO_A   (64 * ROWB2)          // 4096
#define TO_B   (128 * ROWB2)         // 8192
#define STAGEO (TO_A + 2 * TO_B)     // 20480
#define SMEMO  (3 * STAGEO)          // 61440

// ---- EPI3 1-term geometry: KC=64, 128B rows, SW128 ----
#define KC1    64
#define ROWB1  128
#define T1_B   (128 * ROWB1)         // 16384
#define STAGE1 (2 * T1_B)            // 32768
#define SMEM1  (3 * STAGE1)          // 98304

// ---- EPI1 1-term geometry: tile 64x128, KC=64, 3 CTAs/SM ----
#define TE_A   (64 * ROWB1)          // 8192
#define TE_B   (128 * ROWB1)         // 16384
#define STAGEE (TE_A + TE_B)         // 24576
#define SMEME  (3 * STAGEE)          // 73728

// state
__device__ __align__(16) __half g_bh[(size_t)MDIM * DLCA];   // b in fp16
__device__ __align__(16) float  g_u[(size_t)MDIM * DLCA];
__device__ float g_diag[DLCA];
// fp16 operands
__device__ __align__(16) __half g_ahi[(size_t)MDIM * DLCA];
__device__ __align__(16) __half g_thi[(size_t)MDIM * DMODEL];
__device__ __align__(16) __half g_xhi[(size_t)MDIM * DMODEL];
__device__ __align__(16) __half g_Whi[(size_t)DMODEL * DLCA];
__device__ __align__(16) __half g_Wlo[(size_t)DMODEL * DLCA];
__device__ __align__(16) __half g_Wthi[(size_t)DLCA * DMODEL];
__device__ __align__(16) __half g_Wtlo[(size_t)DLCA * DMODEL];

__device__ __forceinline__ uint32_t smem_u32(const void* p) {
    uint32_t a;
    asm("{ .reg .u64 t; cvta.to.shared.u64 t, %1; cvt.u32.u64 %0, t; }" : "=r"(a) : "l"(p));
    return a;
}
__device__ __forceinline__ void ldsm4(uint32_t r[4], uint32_t addr) {
    asm volatile("ldmatrix.sync.aligned.m8n8.x4.shared.b16 {%0,%1,%2,%3}, [%4];"
                 : "=r"(r[0]), "=r"(r[1]), "=r"(r[2]), "=r"(r[3]) : "r"(addr));
}
__device__ __forceinline__ void mma16816(float c[4], const uint32_t a[4], const uint32_t b[2]) {
    asm volatile("mma.sync.aligned.m16n8k16.row.col.f32.f16.f16.f32 "
                 "{%0,%1,%2,%3}, {%4,%5,%6,%7}, {%8,%9}, {%0,%1,%2,%3};"
                 : "+f"(c[0]), "+f"(c[1]), "+f"(c[2]), "+f"(c[3])
                 : "r"(a[0]), "r"(a[1]), "r"(a[2]), "r"(a[3]), "r"(b[0]), "r"(b[1]));
}
#define CP_ASYNC(dst, src) \
    asm volatile("cp.async.cg.shared.global [%0], [%1], 16;" :: "r"(dst), "l"(src) : "memory")
#define CP_COMMIT() asm volatile("cp.async.commit_group;" ::: "memory")
#define CP_WAIT1()  asm volatile("cp.async.wait_group 1;" ::: "memory")
#define CP_WAIT2()  asm volatile("cp.async.wait_group 2;" ::: "memory")

// ---------------- prep kernels ----------------
__global__ void split_x_kernel(const float* __restrict__ x) {
    size_t i = (size_t)blockIdx.x * blockDim.x + threadIdx.x;
    g_xhi[i] = __float2half_rn(x[i]);
}
__global__ void splitW_kernel(const float* __restrict__ W) {
    __shared__ float tile[32][33];
    int n0 = blockIdx.x * 32, k0 = blockIdx.y * 32;
    int tx = threadIdx.x, ty = threadIdx.y;
    #pragma unroll
    for (int r = 0; r < 4; r++) {
        int k = k0 + ty + r * 8;
        float v = W[(size_t)k * DLCA + n0 + tx];
        __half h = __float2half_rn(v);
        g_Whi[(size_t)k * DLCA + n0 + tx] = h;
        g_Wlo[(size_t)k * DLCA + n0 + tx] = __float2half_rn(v - __half2float(h));
        tile[ty + r * 8][tx] = v;
    }
    __syncthreads();
    #pragma unroll
    for (int r = 0; r < 4; r++) {
        int n = n0 + ty + r * 8;
        float v = tile[tx][ty + r * 8];
        __half h = __float2half_rn(v);
        g_Wthi[(size_t)n * DMODEL + k0 + tx] = h;
        g_Wtlo[(size_t)n * DMODEL + k0 + tx] = __float2half_rn(v - __half2float(h));
    }
}
__global__ void diag_kernel(const float* __restrict__ W) {
    int j = blockIdx.x * blockDim.x + threadIdx.x;
    float s = 0.0f;
    #pragma unroll 8
    for (int k = 0; k < DMODEL; k++) {
        float w = W[(size_t)k * DLCA + j];
        s = fmaf(w, w, s);
    }
    g_diag[j] = s;
}

// ========== EPI0: b-init 2-term GEMM (128x128, KC=32, 4-stage, 128thr) ==========
// D = xh*(Wth + Wtl); b=fp16(D); u=0.1 D; a=relu(u-lam)
__global__ __launch_bounds__(128, 2)
void lca_gemm_binit()
{
    constexpr int Kdim = DMODEL;
    constexpr int Nout = DLCA;
    constexpr int NC   = Kdim / KC2;

    extern __shared__ __align__(16) char smem[];
    const uint32_t sbase = smem_u32(smem);

    const int tid = threadIdx.x;
    const int wid = tid >> 5, l = tid & 31;
    const int wm = wid >> 1, wn = wid & 1;      // 2x2, warp tile 64x64
    const int mBase = blockIdx.y * 128;
    const int nBase = blockIdx.x * 128;

    const __half* Ah = g_xhi + (size_t)mBase * Kdim;
    const __half* Bh = g_Wthi + (size_t)nBase * Kdim;
    const __half* Bl = g_Wtlo + (size_t)nBase * Kdim;

    auto load_stage = [&](int s, int k0) {
        uint32_t sb = sbase + s * STAGE2;
        #pragma unroll
        for (int i = 0; i < 4; i++) {
            int u = tid + i * 128;
            int r = u >> 2, cc = u & 3;
            uint32_t so = r * ROWB2 + (cc ^ ((r >> 1) & 3)) * 16;
            size_t   go = (size_t)r * Kdim + k0 + cc * 8;
            CP_ASYNC(sb + so, Ah + go);
            CP_ASYNC(sb + T2_B + so, Bh + go);
            CP_ASYNC(sb + 2 * T2_B + so, Bl + go);
        }
    };

    float acc[4][8][4];
    #pragma unroll
    for (int a = 0; a < 4; a++)
        #pragma unroll
        for (int b = 0; b < 8; b++)
            #pragma unroll
            for (int c = 0; c < 4; c++) acc[a][b][c] = 0.0f;

    const int rowA = wm * 64 + (l & 15);
    const uint32_t sA = (uint32_t)((rowA >> 1) & 3);
    const uint32_t aRow = (uint32_t)rowA * ROWB2;
    const int colA0 = l >> 4;
    const int gB = l >> 3;
    const int rowB = wn * 64 + (l & 7) + (gB >> 1) * 8;
    const uint32_t sB = (uint32_t)((rowB >> 1) & 3);
    const uint32_t bRow = (uint32_t)rowB * ROWB2;
    const int colB0 = gB & 1;

    load_stage(0, 0);       CP_COMMIT();
    load_stage(1, KC2);     CP_COMMIT();
    load_stage(2, 2 * KC2); CP_COMMIT();

    for (int c = 0; c < NC; c++) {
        CP_WAIT2();
        __syncthreads();
        if (c + 3 < NC) load_stage((c + 3) % NST2, (c + 3) * KC2);
        CP_COMMIT();

        uint32_t st = sbase + (c % NST2) * STAGE2;
        #pragma unroll
        for (int k16 = 0; k16 < 2; k16++) {
            const uint32_t cA = (uint32_t)((colA0 + k16 * 2)) ^ sA;
            const uint32_t cB = (uint32_t)((colB0 + k16 * 2)) ^ sB;
            uint32_t aH = st + aRow + cA * 16;
            uint32_t bH = st + T2_B + bRow + cB * 16;
            uint32_t bL = st + 2 * T2_B + bRow + cB * 16;
            uint32_t ah[4][4], bh[4][4], bl[4][4];
            #pragma unroll
            for (int mt = 0; mt < 4; mt++) ldsm4(ah[mt], aH + mt * (16 * ROWB2));
            #pragma unroll
            for (int p = 0; p < 4; p++)    ldsm4(bh[p], bH + p * (16 * ROWB2));
            #pragma unroll
            for (int mt = 0; mt < 4; mt++)
                #pragma unroll
                for (int nt = 0; nt < 8; nt++)
                    mma16816(acc[mt][nt], ah[mt], &bh[nt >> 1][(nt & 1) * 2]);
            #pragma unroll
            for (int p = 0; p < 4; p++)    ldsm4(bl[p], bL + p * (16 * ROWB2));
            #pragma unroll
            for (int mt = 0; mt < 4; mt++)
                #pragma unroll
                for (int nt = 0; nt < 8; nt++)
                    mma16816(acc[mt][nt], ah[mt], &bl[nt >> 1][(nt & 1) * 2]);
        }
    }

    const int rb = wm * 64 + (l >> 2);
    const int cb = wn * 64 + 2 * (l & 3);
    #pragma unroll
    for (int mt = 0; mt < 4; mt++)
        #pragma unroll
        for (int i2 = 0; i2 < 2; i2++) {
            int row = mBase + rb + mt * 16 + i2 * 8;
            #pragma unroll
            for (int nt = 0; nt < 8; nt++) {
                int col = nBase + cb + nt * 8;
                size_t idx = (size_t)row * Nout + col;
                float v0 = acc[mt][nt][2 * i2], v1 = acc[mt][nt][2 * i2 + 1];
                *(__half2*)&g_bh[idx] = __halves2half2(
                    __float2half_rn(v0), __float2half_rn(v1));
                float u0 = RATEV * v0, u1 = RATEV * v1;
                *(float2*)&g_u[idx] = make_float2(u0, u1);
                float a0 = fmaxf(u0 - LAMV, 0.0f), a1 = fmaxf(u1 - LAMV, 0.0f);
                *(__half2*)&g_ahi[idx] = __halves2half2(
                    __float2half_rn(a0), __float2half_rn(a1));
            }
        }
}

// ========== EPI2: out 2-term GEMM (64x128 tile, KC=32, 3-stage, 3 CTAs/SM) =====
// out = ah*(Wh + Wl), fp32
__global__ __launch_bounds__(128, 3)
void lca_gemm_out(float* __restrict__ outp)
{
    constexpr int Kdim = DLCA;
    constexpr int Nout = DMODEL;
    constexpr int NC   = Kdim / KC2;

    extern __shared__ __align__(16) char smem[];
    const uint32_t sbase = smem_u32(smem);

    const int tid = threadIdx.x;
    const int wid = tid >> 5, l = tid & 31;     // 4 warps, 1m x 4n, warp tile 64x32
    const int wn = wid;
    const int mBase = blockIdx.y * 64;
    const int nBase = blockIdx.x * 128;

    const __half* Ah = g_ahi + (size_t)mBase * Kdim;
    const __half* Bh = g_Whi + (size_t)nBase * Kdim;
    const __half* Bl = g_Wlo + (size_t)nBase * Kdim;

    // stage: [A 64r][Bh 128r][Bl 128r], ROWB2=64B rows
    auto load_stage = [&](int s, int k0) {
        uint32_t sb = sbase + s * STAGEO;
        #pragma unroll
        for (int i = 0; i < 2; i++) {           // A: 256 units
            int u = tid + i * 128;
            int r = u >> 2, cc = u & 3;
            uint32_t so = r * ROWB2 + (cc ^ ((r >> 1) & 3)) * 16;
            CP_ASYNC(sb + so, Ah + (size_t)r * Kdim + k0 + cc * 8);
        }
        #pragma unroll
        for (int i = 0; i < 4; i++) {           // Bh/Bl: 512 units each
            int u = tid + i * 128;
            int r = u >> 2, cc = u & 3;
            uint32_t so = r * ROWB2 + (cc ^ ((r >> 1) & 3)) * 16;
            size_t   go = (size_t)r * Kdim + k0 + cc * 8;
            CP_ASYNC(sb + TO_A + so, Bh + go);
            CP_ASYNC(sb + TO_A + TO_B + so, Bl + go);
        }
    };

    float acc[4][4][4];
    #pragma unroll
    for (int a = 0; a < 4; a++)
        #pragma unroll
        for (int b = 0; b < 4; b++)
            #pragma unroll
            for (int c = 0; c < 4; c++) acc[a][b][c] = 0.0f;

    const int rowA = l & 15;
    const uint32_t sA = (uint32_t)((rowA >> 1) & 3);
    const uint32_t aRow = (uint32_t)rowA * ROWB2;
    const int colA0 = l >> 4;
    const int gB = l >> 3;
    const int rowB = wn * 32 + (l & 7) + (gB >> 1) * 8;
    const uint32_t sB = (uint32_t)((rowB >> 1) & 3);
    const uint32_t bRow = (uint32_t)rowB * ROWB2;
    const int colB0 = gB & 1;

    load_stage(0, 0);   CP_COMMIT();
    load_stage(1, KC2); CP_COMMIT();

    for (int c = 0; c < NC; c++) {
        CP_WAIT1();
        __syncthreads();
        if (c + 2 < NC) load_stage((c + 2) % 3, (c + 2) * KC2);
        CP_COMMIT();

        uint32_t st = sbase + (c % 3) * STAGEO;
        #pragma unroll
        for (int k16 = 0; k16 < 2; k16++) {
            const uint32_t cA = (uint32_t)((colA0 + k16 * 2)) ^ sA;
            const uint32_t cB = (uint32_t)((colB0 + k16 * 2)) ^ sB;
            uint32_t aH = st + aRow + cA * 16;
            uint32_t bH = st + TO_A + bRow + cB * 16;
            uint32_t bL = st + TO_A + TO_B + bRow + cB * 16;
            uint32_t ah[4][4], bh[2][4], bl[2][4];
            #pragma unroll
            for (int mt = 0; mt < 4; mt++) ldsm4(ah[mt], aH + mt * (16 * ROWB2));
            #pragma unroll
            for (int p = 0; p < 2; p++)    ldsm4(bh[p], bH + p * (16 * ROWB2));
            #pragma unroll
            for (int mt = 0; mt < 4; mt++)
                #pragma unroll
                for (int nt = 0; nt < 4; nt++)
                    mma16816(acc[mt][nt], ah[mt], &bh[nt >> 1][(nt & 1) * 2]);
            #pragma unroll
            for (int p = 0; p < 2; p++)    ldsm4(bl[p], bL + p * (16 * ROWB2));
            #pragma unroll
            for (int mt = 0; mt < 4; mt++)
                #pragma unroll
                for (int nt = 0; nt < 4; nt++)
                    mma16816(acc[mt][nt], ah[mt], &bl[nt >> 1][(nt & 1) * 2]);
        }
    }

    const int rb = l >> 2;
    const int cb = wn * 32 + 2 * (l & 3);
    #pragma unroll
    for (int mt = 0; mt < 4; mt++)
        #pragma unroll
        for (int i2 = 0; i2 < 2; i2++) {
            int row = mBase + rb + mt * 16 + i2 * 8;
            #pragma unroll
            for (int nt = 0; nt < 4; nt++) {
                int col = nBase + cb + nt * 8;
                size_t idx = (size_t)row * Nout + col;
                *(float2*)&outp[idx] = make_float2(acc[mt][nt][2 * i2],
                                                   acc[mt][nt][2 * i2 + 1]);
            }
        }
}

// ========== EPI3: u-update 1-term GEMM (256thr, 64x32 warp) ==========
// (A=thi, B=Wthi, K=1024, Nout=4096); b read as fp16
__global__ __launch_bounds__(256, 2)
void lca_gemm_upd()
{
    constexpr int Kdim = DMODEL;
    constexpr int Nout = DLCA;
    constexpr int NC   = Kdim / KC1;

    extern __shared__ __align__(16) char smem[];
    const uint32_t sbase = smem_u32(smem);

    const int tid = threadIdx.x;
    const int wid = tid >> 5, l = tid & 31;
    const int wm = wid >> 2, wn = wid & 3;
    const int mBase = blockIdx.y * 128;
    const int nBase = blockIdx.x * 128;

    const __half* Ah = g_thi + (size_t)mBase * Kdim;
    const __half* Bh = g_Wthi + (size_t)nBase * Kdim;

    auto load_stage = [&](int s, int k0) {
        uint32_t sb = sbase + s * STAGE1;
        #pragma unroll
        for (int i = 0; i < 4; i++) {
            int u = tid + i * 256;
            int r = u >> 3, cc = u & 7;
            uint32_t so = r * ROWB1 + (cc ^ (r & 7)) * 16;
            size_t   go = (size_t)r * Kdim + k0 + cc * 8;
            CP_ASYNC(sb + so, Ah + go);
            CP_ASYNC(sb + T1_B + so, Bh + go);
        }
    };

    float acc[4][4][4];
    #pragma unroll
    for (int a = 0; a < 4; a++)
        #pragma unroll
        for (int b = 0; b < 4; b++)
            #pragma unroll
            for (int c = 0; c < 4; c++) acc[a][b][c] = 0.0f;

    const int rowA = wm * 64 + (l & 15);
    const uint32_t sA = (uint32_t)(rowA & 7);
    const uint32_t aRow = (uint32_t)rowA * ROWB1;
    const int colA0 = l >> 4;
    const int gB = l >> 3;
    const int rowB = wn * 32 + (l & 7) + (gB >> 1) * 8;
    const uint32_t sB = (uint32_t)(rowB & 7);
    const uint32_t bRow = (uint32_t)rowB * ROWB1;
    const int colB0 = gB & 1;

    load_stage(0, 0);   CP_COMMIT();
    load_stage(1, KC1); CP_COMMIT();

    for (int c = 0; c < NC; c++) {
        CP_WAIT1();
        __syncthreads();
        if (c + 2 < NC) load_stage((c + 2) % 3, (c + 2) * KC1);
        CP_COMMIT();

        uint32_t st = sbase + (c % 3) * STAGE1;
        #pragma unroll
        for (int k16 = 0; k16 < 4; k16++) {
            const uint32_t cA = (uint32_t)((colA0 + k16 * 2)) ^ sA;
            const uint32_t cB = (uint32_t)((colB0 + k16 * 2)) ^ sB;
            uint32_t aH = st + aRow + cA * 16;
            uint32_t bH = st + T1_B + bRow + cB * 16;
            uint32_t ah[4][4], bh[2][4];
            #pragma unroll
            for (int mt = 0; mt < 4; mt++) ldsm4(ah[mt], aH + mt * (16 * ROWB1));
            #pragma unroll
            for (int p = 0; p < 2; p++)    ldsm4(bh[p], bH + p * (16 * ROWB1));
            #pragma unroll
            for (int mt = 0; mt < 4; mt++)
                #pragma unroll
                for (int nt = 0; nt < 4; nt++)
                    mma16816(acc[mt][nt], ah[mt], &bh[nt >> 1][(nt & 1) * 2]);
        }
    }

    const int rb = wm * 64 + (l >> 2);
    const int cb = wn * 32 + 2 * (l & 3);
    #pragma unroll
    for (int mt = 0; mt < 4; mt++)
        #pragma unroll
        for (int i2 = 0; i2 < 2; i2++) {
            int row = mBase + rb + mt * 16 + i2 * 8;
            #pragma unroll
            for (int nt = 0; nt < 4; nt++) {
                int col = nBase + cb + nt * 8;
                size_t idx = (size_t)row * Nout + col;
                float v0 = acc[mt][nt][2 * i2], v1 = acc[mt][nt][2 * i2 + 1];
                __half2 bh2 = *(__half2*)&g_bh[idx];
                float2 uu = *(float2*)&g_u[idx];
                float b0 = __half2float(__low2half(bh2));
                float b1 = __half2float(__high2half(bh2));
                float d0 = g_diag[col], d1 = g_diag[col + 1];
                float ao0 = fmaxf(uu.x - LAMV, 0.0f), ao1 = fmaxf(uu.y - LAMV, 0.0f);
                float aG0 = v0 - ao0 * d0, aG1 = v1 - ao1 * d1;
                float un0 = uu.x + RATEV * (b0 - aG0 - uu.x);
                float un1 = uu.y + RATEV * (b1 - aG1 - uu.y);
                *(float2*)&g_u[idx] = make_float2(un0, un1);
                float a0 = fmaxf(un0 - LAMV, 0.0f), a1 = fmaxf(un1 - LAMV, 0.0f);
                *(__half2*)&g_ahi[idx] = __halves2half2(
                    __float2half_rn(a0), __float2half_rn(a1));
            }
        }
}

// ========== EPI1: t GEMM, tile 64x128, 128thr, 3 CTAs/SM ==========
__global__ __launch_bounds__(128, 3)
void lca_gemm_t()
{
    constexpr int Kdim = DLCA;
    constexpr int Nout = DMODEL;
    constexpr int NC   = Kdim / KC1;

    extern __shared__ __align__(16) char smem[];
    const uint32_t sbase = smem_u32(smem);

    const int tid = threadIdx.x;
    const int wid = tid >> 5, l = tid & 31;
    const int wn = wid;
    const int mBase = blockIdx.y * 64;
    const int nBase = blockIdx.x * 128;

    const __half* Ah = g_ahi + (size_t)mBase * Kdim;
    const __half* Bh = g_Whi + (size_t)nBase * Kdim;

    auto load_stage = [&](int s, int k0) {
        uint32_t sb = sbase + s * STAGEE;
        #pragma unroll
        for (int i = 0; i < 4; i++) {
            int u = tid + i * 128;
            int r = u >> 3, cc = u & 7;
            uint32_t so = r * ROWB1 + (cc ^ (r & 7)) * 16;
            CP_ASYNC(sb + so, Ah + (size_t)r * Kdim + k0 + cc * 8);
        }
        #pragma unroll
        for (int i = 0; i < 8; i++) {
            int u = tid + i * 128;
            int r = u >> 3, cc = u & 7;
            uint32_t so = r * ROWB1 + (cc ^ (r & 7)) * 16;
            CP_ASYNC(sb + TE_A + so, Bh + (size_t)r * Kdim + k0 + cc * 8);
        }
    };

    float acc[4][4][4];
    #pragma unroll
    for (int a = 0; a < 4; a++)
        #pragma unroll
        for (int b = 0; b < 4; b++)
            #pragma unroll
            for (int c = 0; c < 4; c++) acc[a][b][c] = 0.0f;

    const int rowA = l & 15;
    const uint32_t sA = (uint32_t)(rowA & 7);
    const uint32_t aRow = (uint32_t)rowA * ROWB1;
    const int colA0 = l >> 4;
    const int gB = l >> 3;
    const int rowB = wn * 32 + (l & 7) + (gB >> 1) * 8;
    const uint32_t sB = (uint32_t)(rowB & 7);
    const uint32_t bRow = (uint32_t)rowB * ROWB1;
    const int colB0 = gB & 1;

    load_stage(0, 0);   CP_COMMIT();
    load_stage(1, KC1); CP_COMMIT();

    for (int c = 0; c < NC; c++) {
        CP_WAIT1();
        __syncthreads();
        if (c + 2 < NC) load_stage((c + 2) % 3, (c + 2) * KC1);
        CP_COMMIT();

        uint32_t st = sbase + (c % 3) * STAGEE;
        #pragma unroll
        for (int k16 = 0; k16 < 4; k16++) {
            const uint32_t cA = (uint32_t)((colA0 + k16 * 2)) ^ sA;
            const uint32_t cB = (uint32_t)((colB0 + k16 * 2)) ^ sB;
            uint32_t aH = st + aRow + cA * 16;
            uint32_t bH = st + TE_A + bRow + cB * 16;
            uint32_t ah[4][4], bh[2][4];
            #pragma unroll
            for (int mt = 0; mt < 4; mt++) ldsm4(ah[mt], aH + mt * (16 * ROWB1));
            #pragma unroll
            for (int p = 0; p < 2; p++)    ldsm4(bh[p], bH + p * (16 * ROWB1));
            #pragma unroll
            for (int mt = 0; mt < 4; mt++)
                #pragma unroll
                for (int nt = 0; nt < 4; nt++)
                    mma16816(acc[mt][nt], ah[mt], &bh[nt >> 1][(nt & 1) * 2]);
        }
    }

    const int rb = l >> 2;
    const int cb = wn * 32 + 2 * (l & 3);
    #pragma unroll
    for (int mt = 0; mt < 4; mt++)
        #pragma unroll
        for (int i2 = 0; i2 < 2; i2++) {
            int row = mBase + rb + mt * 16 + i2 * 8;
            #pragma unroll
            for (int nt = 0; nt < 4; nt++) {
                int col = nBase + cb + nt * 8;
                size_t idx = (size_t)row * Nout + col;
                *(__half2*)&g_thi[idx] = __halves2half2(
                    __float2half_rn(acc[mt][nt][2 * i2]),
                    __float2half_rn(acc[mt][nt][2 * i2 + 1]));
            }
        }
}

// ---------------- launch ----------------
extern "C" void kernel_launch(void* const* d_in, const int* in_sizes, int n_in,
                              void* d_out, int out_size)
{
    const float* x = (const float*)d_in[0];
    const float* W = (const float*)d_in[1];
    if (n_in >= 2 && in_sizes[0] < in_sizes[1]) { const float* t = x; x = W; W = t; }
    float* out = (float*)d_out;

    cudaFuncSetAttribute(lca_gemm_binit, cudaFuncAttributeMaxDynamicSharedMemorySize, SMEM2T);
    cudaFuncSetAttribute(lca_gemm_out,   cudaFuncAttributeMaxDynamicSharedMemorySize, SMEMO);
    cudaFuncSetAttribute(lca_gemm_upd,   cudaFuncAttributeMaxDynamicSharedMemorySize, SMEM1);
    cudaFuncSetAttribute(lca_gemm_t,     cudaFuncAttributeMaxDynamicSharedMemorySize, SMEME);

    split_x_kernel<<<(MDIM * DMODEL) / 256, 256>>>(x);
    splitW_kernel<<<dim3(DLCA / 32, DMODEL / 32), dim3(32, 8)>>>(W);
    diag_kernel<<<DLCA / 256, 256>>>(W);

    dim3 gridB(DLCA / 128, MDIM / 128);     // (32, 64)
    dim3 gridT(DMODEL / 128, MDIM / 64);    // (8, 128) = 1024 CTAs
    dim3 gridO(DMODEL / 128, MDIM / 64);    // (8, 128) = 1024 CTAs

    lca_gemm_binit<<<gridB, 128, SMEM2T>>>();
    for (int s = 0; s < 9; s++) {
        lca_gemm_t<<<gridT, 128, SMEME>>>();
        lca_gemm_upd<<<gridB, 256, SMEM1>>>();
    }
    lca_gemm_out<<<gridO, 128, SMEMO>>>(out);
}

// round 16
// speedup vs baseline: 1.2829x; 1.0794x over previous
#include <cuda_runtime.h>
#include <cuda_fp16.h>
#include <cstdint>

// LCA layer via mma.sync (HMMA), factored + precision-budgeted:
//   b = x@W~ ; u1 = 0.1 b ; 9x { t = a@W~^T ; u += 0.1(b - (tW~ - a*diag) - u) }
//   out = a@W~^T      (W~ = fp16(W) everywhere; all GEMMs 1-term fp16, fp32 accum)
// R16: dropped W-lo from binit and out (all 1-term). binit reuses the EPI3
//      geometry; out reuses the EPI1 geometry. rel_err budget ~4.6e-4.

#define MDIM   8192
#define DMODEL 1024
#define DLCA   4096
#define LAMV   0.1f
#define RATEV  0.1f

// ---- 1-term 128x128 geometry: KC=64, 128B rows, SW128 c^(r&7) ----
#define KC1    64
#define ROWB1  128
#define T1_B   (128 * ROWB1)         // 16384
#define STAGE1 (2 * T1_B)            // 32768
#define SMEM1  (3 * STAGE1)          // 98304

// ---- 1-term 64x128 geometry (EPI1/out): KC=64, 3 CTAs/SM ----
#define TE_A   (64 * ROWB1)          // 8192
#define TE_B   (128 * ROWB1)         // 16384
#define STAGEE (TE_A + TE_B)         // 24576
#define SMEME  (3 * STAGEE)          // 73728

// state
__device__ __align__(16) __half g_bh[(size_t)MDIM * DLCA];   // b in fp16
__device__ __align__(16) float  g_u[(size_t)MDIM * DLCA];
__device__ float g_diag[DLCA];
// fp16 operands
__device__ __align__(16) __half g_ahi[(size_t)MDIM * DLCA];
__device__ __align__(16) __half g_thi[(size_t)MDIM * DMODEL];
__device__ __align__(16) __half g_xhi[(size_t)MDIM * DMODEL];
__device__ __align__(16) __half g_Whi[(size_t)DMODEL * DLCA];
__device__ __align__(16) __half g_Wthi[(size_t)DLCA * DMODEL];

__device__ __forceinline__ uint32_t smem_u32(const void* p) {
    uint32_t a;
    asm("{ .reg .u64 t; cvta.to.shared.u64 t, %1; cvt.u32.u64 %0, t; }" : "=r"(a) : "l"(p));
    return a;
}
__device__ __forceinline__ void ldsm4(uint32_t r[4], uint32_t addr) {
    asm volatile("ldmatrix.sync.aligned.m8n8.x4.shared.b16 {%0,%1,%2,%3}, [%4];"
                 : "=r"(r[0]), "=r"(r[1]), "=r"(r[2]), "=r"(r[3]) : "r"(addr));
}
__device__ __forceinline__ void mma16816(float c[4], const uint32_t a[4], const uint32_t b[2]) {
    asm volatile("mma.sync.aligned.m16n8k16.row.col.f32.f16.f16.f32 "
                 "{%0,%1,%2,%3}, {%4,%5,%6,%7}, {%8,%9}, {%0,%1,%2,%3};"
                 : "+f"(c[0]), "+f"(c[1]), "+f"(c[2]), "+f"(c[3])
                 : "r"(a[0]), "r"(a[1]), "r"(a[2]), "r"(a[3]), "r"(b[0]), "r"(b[1]));
}
#define CP_ASYNC(dst, src) \
    asm volatile("cp.async.cg.shared.global [%0], [%1], 16;" :: "r"(dst), "l"(src) : "memory")
#define CP_COMMIT() asm volatile("cp.async.commit_group;" ::: "memory")
#define CP_WAIT1()  asm volatile("cp.async.wait_group 1;" ::: "memory")

// ---------------- prep kernels ----------------
__global__ void split_x_kernel(const float* __restrict__ x) {
    size_t i = (size_t)blockIdx.x * blockDim.x + threadIdx.x;
    g_xhi[i] = __float2half_rn(x[i]);
}
__global__ void splitW_kernel(const float* __restrict__ W) {
    __shared__ float tile[32][33];
    int n0 = blockIdx.x * 32, k0 = blockIdx.y * 32;
    int tx = threadIdx.x, ty = threadIdx.y;
    #pragma unroll
    for (int r = 0; r < 4; r++) {
        int k = k0 + ty + r * 8;
        float v = W[(size_t)k * DLCA + n0 + tx];
        g_Whi[(size_t)k * DLCA + n0 + tx] = __float2half_rn(v);
        tile[ty + r * 8][tx] = v;
    }
    __syncthreads();
    #pragma unroll
    for (int r = 0; r < 4; r++) {
        int n = n0 + ty + r * 8;
        float v = tile[tx][ty + r * 8];
        g_Wthi[(size_t)n * DMODEL + k0 + tx] = __float2half_rn(v);
    }
}
__global__ void diag_kernel(const float* __restrict__ W) {
    int j = blockIdx.x * blockDim.x + threadIdx.x;
    float s = 0.0f;
    #pragma unroll 8
    for (int k = 0; k < DMODEL; k++) {
        float w = W[(size_t)k * DLCA + j];
        s = fmaf(w, w, s);
    }
    g_diag[j] = s;
}

// ========== 128x128 1-term GEMM (KC=64, 3-stage, 256thr, 64x32 warp) ==========
// EPI 0 (binit): A=xhi, B=Wthi, K=1024, Nout=4096 -> bh, u=0.1v, ahi
// EPI 3 (upd):   A=thi, B=Wthi, K=1024, Nout=4096 -> u update; ahi
template <int EPI>
__global__ __launch_bounds__(256, 2)
void lca_gemm_big()
{
    constexpr int Kdim = DMODEL;
    constexpr int Nout = DLCA;
    constexpr int NC   = Kdim / KC1;

    const __half* Ahp = (EPI == 0) ? g_xhi : g_thi;

    extern __shared__ __align__(16) char smem[];
    const uint32_t sbase = smem_u32(smem);

    const int tid = threadIdx.x;
    const int wid = tid >> 5, l = tid & 31;
    const int wm = wid >> 2, wn = wid & 3;
    const int mBase = blockIdx.y * 128;
    const int nBase = blockIdx.x * 128;

    const __half* Ah = Ahp + (size_t)mBase * Kdim;
    const __half* Bh = g_Wthi + (size_t)nBase * Kdim;

    auto load_stage = [&](int s, int k0) {
        uint32_t sb = sbase + s * STAGE1;
        #pragma unroll
        for (int i = 0; i < 4; i++) {
            int u = tid + i * 256;
            int r = u >> 3, cc = u & 7;
            uint32_t so = r * ROWB1 + (cc ^ (r & 7)) * 16;
            size_t   go = (size_t)r * Kdim + k0 + cc * 8;
            CP_ASYNC(sb + so, Ah + go);
            CP_ASYNC(sb + T1_B + so, Bh + go);
        }
    };

    float acc[4][4][4];
    #pragma unroll
    for (int a = 0; a < 4; a++)
        #pragma unroll
        for (int b = 0; b < 4; b++)
            #pragma unroll
            for (int c = 0; c < 4; c++) acc[a][b][c] = 0.0f;

    const int rowA = wm * 64 + (l & 15);
    const uint32_t sA = (uint32_t)(rowA & 7);
    const uint32_t aRow = (uint32_t)rowA * ROWB1;
    const int colA0 = l >> 4;
    const int gB = l >> 3;
    const int rowB = wn * 32 + (l & 7) + (gB >> 1) * 8;
    const uint32_t sB = (uint32_t)(rowB & 7);
    const uint32_t bRow = (uint32_t)rowB * ROWB1;
    const int colB0 = gB & 1;

    load_stage(0, 0);   CP_COMMIT();
    load_stage(1, KC1); CP_COMMIT();

    for (int c = 0; c < NC; c++) {
        CP_WAIT1();
        __syncthreads();
        if (c + 2 < NC) load_stage((c + 2) % 3, (c + 2) * KC1);
        CP_COMMIT();

        uint32_t st = sbase + (c % 3) * STAGE1;
        #pragma unroll
        for (int k16 = 0; k16 < 4; k16++) {
            const uint32_t cA = (uint32_t)((colA0 + k16 * 2)) ^ sA;
            const uint32_t cB = (uint32_t)((colB0 + k16 * 2)) ^ sB;
            uint32_t aH = st + aRow + cA * 16;
            uint32_t bH = st + T1_B + bRow + cB * 16;
            uint32_t ah[4][4], bh[2][4];
            #pragma unroll
            for (int mt = 0; mt < 4; mt++) ldsm4(ah[mt], aH + mt * (16 * ROWB1));
            #pragma unroll
            for (int p = 0; p < 2; p++)    ldsm4(bh[p], bH + p * (16 * ROWB1));
            #pragma unroll
            for (int mt = 0; mt < 4; mt++)
                #pragma unroll
                for (int nt = 0; nt < 4; nt++)
                    mma16816(acc[mt][nt], ah[mt], &bh[nt >> 1][(nt & 1) * 2]);
        }
    }

    const int rb = wm * 64 + (l >> 2);
    const int cb = wn * 32 + 2 * (l & 3);
    #pragma unroll
    for (int mt = 0; mt < 4; mt++)
        #pragma unroll
        for (int i2 = 0; i2 < 2; i2++) {
            int row = mBase + rb + mt * 16 + i2 * 8;
            #pragma unroll
            for (int nt = 0; nt < 4; nt++) {
                int col = nBase + cb + nt * 8;
                size_t idx = (size_t)row * Nout + col;
                float v0 = acc[mt][nt][2 * i2], v1 = acc[mt][nt][2 * i2 + 1];
                if (EPI == 0) {
                    *(__half2*)&g_bh[idx] = __halves2half2(
                        __float2half_rn(v0), __float2half_rn(v1));
                    float u0 = RATEV * v0, u1 = RATEV * v1;
                    *(float2*)&g_u[idx] = make_float2(u0, u1);
                    float a0 = fmaxf(u0 - LAMV, 0.0f), a1 = fmaxf(u1 - LAMV, 0.0f);
                    *(__half2*)&g_ahi[idx] = __halves2half2(
                        __float2half_rn(a0), __float2half_rn(a1));
                } else {
                    __half2 bh2 = *(__half2*)&g_bh[idx];
                    float2 uu = *(float2*)&g_u[idx];
                    float b0 = __half2float(__low2half(bh2));
                    float b1 = __half2float(__high2half(bh2));
                    float d0 = g_diag[col], d1 = g_diag[col + 1];
                    float ao0 = fmaxf(uu.x - LAMV, 0.0f), ao1 = fmaxf(uu.y - LAMV, 0.0f);
                    float aG0 = v0 - ao0 * d0, aG1 = v1 - ao1 * d1;
                    float un0 = uu.x + RATEV * (b0 - aG0 - uu.x);
                    float un1 = uu.y + RATEV * (b1 - aG1 - uu.y);
                    *(float2*)&g_u[idx] = make_float2(un0, un1);
                    float a0 = fmaxf(un0 - LAMV, 0.0f), a1 = fmaxf(un1 - LAMV, 0.0f);
                    *(__half2*)&g_ahi[idx] = __halves2half2(
                        __float2half_rn(a0), __float2half_rn(a1));
                }
            }
        }
}

// ========== 64x128 1-term GEMM (KC=64, 3-stage, 128thr, 3 CTAs/SM) ==========
// EPI 1 (t):   A=ahi, B=Whi, K=4096, Nout=1024 -> thi fp16
// EPI 2 (out): A=ahi, B=Whi, K=4096, Nout=1024 -> out fp32
template <int EPI>
__global__ __launch_bounds__(128, 3)
void lca_gemm_small(float* __restrict__ outp)
{
    constexpr int Kdim = DLCA;
    constexpr int Nout = DMODEL;
    constexpr int NC   = Kdim / KC1;

    extern __shared__ __align__(16) char smem[];
    const uint32_t sbase = smem_u32(smem);

    const int tid = threadIdx.x;
    const int wid = tid >> 5, l = tid & 31;
    const int wn = wid;                         // 1m x 4n, warp tile 64x32
    const int mBase = blockIdx.y * 64;
    const int nBase = blockIdx.x * 128;

    const __half* Ah = g_ahi + (size_t)mBase * Kdim;
    const __half* Bh = g_Whi + (size_t)nBase * Kdim;

    auto load_stage = [&](int s, int k0) {
        uint32_t sb = sbase + s * STAGEE;
        #pragma unroll
        for (int i = 0; i < 4; i++) {           // A: 512 units
            int u = tid + i * 128;
            int r = u >> 3, cc = u & 7;
            uint32_t so = r * ROWB1 + (cc ^ (r & 7)) * 16;
            CP_ASYNC(sb + so, Ah + (size_t)r * Kdim + k0 + cc * 8);
        }
        #pragma unroll
        for (int i = 0; i < 8; i++) {           // B: 1024 units
            int u = tid + i * 128;
            int r = u >> 3, cc = u & 7;
            uint32_t so = r * ROWB1 + (cc ^ (r & 7)) * 16;
            CP_ASYNC(sb + TE_A + so, Bh + (size_t)r * Kdim + k0 + cc * 8);
        }
    };

    float acc[4][4][4];
    #pragma unroll
    for (int a = 0; a < 4; a++)
        #pragma unroll
        for (int b = 0; b < 4; b++)
            #pragma unroll
            for (int c = 0; c < 4; c++) acc[a][b][c] = 0.0f;

    const int rowA = l & 15;
    const uint32_t sA = (uint32_t)(rowA & 7);
    const uint32_t aRow = (uint32_t)rowA * ROWB1;
    const int colA0 = l >> 4;
    const int gB = l >> 3;
    const int rowB = wn * 32 + (l & 7) + (gB >> 1) * 8;
    const uint32_t sB = (uint32_t)(rowB & 7);
    const uint32_t bRow = (uint32_t)rowB * ROWB1;
    const int colB0 = gB & 1;

    load_stage(0, 0);   CP_COMMIT();
    load_stage(1, KC1); CP_COMMIT();

    for (int c = 0; c < NC; c++) {
        CP_WAIT1();
        __syncthreads();
        if (c + 2 < NC) load_stage((c + 2) % 3, (c + 2) * KC1);
        CP_COMMIT();

        uint32_t st = sbase + (c % 3) * STAGEE;
        #pragma unroll
        for (int k16 = 0; k16 < 4; k16++) {
            const uint32_t cA = (uint32_t)((colA0 + k16 * 2)) ^ sA;
            const uint32_t cB = (uint32_t)((colB0 + k16 * 2)) ^ sB;
            uint32_t aH = st + aRow + cA * 16;
            uint32_t bH = st + TE_A + bRow + cB * 16;
            uint32_t ah[4][4], bh[2][4];
            #pragma unroll
            for (int mt = 0; mt < 4; mt++) ldsm4(ah[mt], aH + mt * (16 * ROWB1));
            #pragma unroll
            for (int p = 0; p < 2; p++)    ldsm4(bh[p], bH + p * (16 * ROWB1));
            #pragma unroll
            for (int mt = 0; mt < 4; mt++)
                #pragma unroll
                for (int nt = 0; nt < 4; nt++)
                    mma16816(acc[mt][nt], ah[mt], &bh[nt >> 1][(nt & 1) * 2]);
        }
    }

    const int rb = l >> 2;
    const int cb = wn * 32 + 2 * (l & 3);
    #pragma unroll
    for (int mt = 0; mt < 4; mt++)
        #pragma unroll
        for (int i2 = 0; i2 < 2; i2++) {
            int row = mBase + rb + mt * 16 + i2 * 8;
            #pragma unroll
            for (int nt = 0; nt < 4; nt++) {
                int col = nBase + cb + nt * 8;
                size_t idx = (size_t)row * Nout + col;
                if (EPI == 1) {
                    *(__half2*)&g_thi[idx] = __halves2half2(
                        __float2half_rn(acc[mt][nt][2 * i2]),
                        __float2half_rn(acc[mt][nt][2 * i2 + 1]));
                } else {
                    *(float2*)&outp[idx] = make_float2(acc[mt][nt][2 * i2],
                                                       acc[mt][nt][2 * i2 + 1]);
                }
            }
        }
}

// ---------------- launch ----------------
extern "C" void kernel_launch(void* const* d_in, const int* in_sizes, int n_in,
                              void* d_out, int out_size)
{
    const float* x = (const float*)d_in[0];
    const float* W = (const float*)d_in[1];
    if (n_in >= 2 && in_sizes[0] < in_sizes[1]) { const float* t = x; x = W; W = t; }
    float* out = (float*)d_out;

    cudaFuncSetAttribute(lca_gemm_big<0>,   cudaFuncAttributeMaxDynamicSharedMemorySize, SMEM1);
    cudaFuncSetAttribute(lca_gemm_big<3>,   cudaFuncAttributeMaxDynamicSharedMemorySize, SMEM1);
    cudaFuncSetAttribute(lca_gemm_small<1>, cudaFuncAttributeMaxDynamicSharedMemorySize, SMEME);
    cudaFuncSetAttribute(lca_gemm_small<2>, cudaFuncAttributeMaxDynamicSharedMemorySize, SMEME);

    split_x_kernel<<<(MDIM * DMODEL) / 256, 256>>>(x);
    splitW_kernel<<<dim3(DLCA / 32, DMODEL / 32), dim3(32, 8)>>>(W);
    diag_kernel<<<DLCA / 256, 256>>>(W);

    dim3 gridB(DLCA / 128, MDIM / 128);     // (32, 64)  = 2048 CTAs
    dim3 gridS(DMODEL / 128, MDIM / 64);    // (8, 128)  = 1024 CTAs

    lca_gemm_big<0><<<gridB, 256, SMEM1>>>();                 // b-init
    for (int s = 0; s < 9; s++) {
        lca_gemm_small<1><<<gridS, 128, SMEME>>>(nullptr);    // t = a @ W~^T
        lca_gemm_big<3><<<gridB, 256, SMEM1>>>();             // u update
    }
    lca_gemm_small<2><<<gridS, 128, SMEME>>>(out);            // out
}